// round 2
// baseline (speedup 1.0000x reference)
#include <cuda_runtime.h>

#define DIM   256
#define BATCH 256
#define MCn   128
#define MPn   256
#define NMAX  20000

// ---------------- static device scratch (no allocations allowed) ----------------
__device__ float g_cq[NMAX*DIM];
__device__ float g_ck[NMAX*DIM];
__device__ float g_cv[NMAX*DIM];
__device__ float g_pq[NMAX*DIM];
__device__ float g_pk[NMAX*DIM];
__device__ float g_pv[NMAX*DIM];
__device__ float g_cf[BATCH*MCn*DIM];   // comp_fused (pre-gate)
__device__ float g_pf[BATCH*MPn*DIM];   // prot_fused (pre-gate)
__device__ float g_gc[BATCH*MCn*DIM];   // gate logits compound
__device__ float g_gp[BATCH*MPn*DIM];   // gate logits protein
__device__ float g_impc[BATCH*MCn];
__device__ float g_impp[BATCH*MPn];

// ---------------- init ----------------
__global__ void init_impp_k() {
    int i = blockIdx.x * blockDim.x + threadIdx.x;
    if (i < BATCH*MPn) g_impp[i] = 0.0f;
}

// ---------------- SGEMM: C[N][256] = X[N][256] @ W[256][256]^T + bias ----------------
__global__ void gemm_nt(const float* __restrict__ X, const float* __restrict__ W,
                        const float* __restrict__ bias, float* __restrict__ C, int N)
{
    __shared__ float sX[16][68];
    __shared__ float sW[16][68];
    const int tid = threadIdx.x;                 // 256 threads
    const int bn  = blockIdx.x * 64;             // out-col base
    const int bm  = blockIdx.y * 64;             // row base
    const int tr  = (tid >> 4) << 2;
    const int tc  = (tid & 15) << 2;
    const int lr  = tid >> 2;                    // 0..63
    const int lc  = (tid & 3) << 2;              // 0,4,8,12
    float acc[4][4] = {};
    for (int k0 = 0; k0 < 256; k0 += 16) {
        float4 xv = make_float4(0.f, 0.f, 0.f, 0.f);
        int xr = bm + lr;
        if (xr < N) xv = *(const float4*)(X + xr*256 + k0 + lc);
        sX[lc+0][lr] = xv.x; sX[lc+1][lr] = xv.y; sX[lc+2][lr] = xv.z; sX[lc+3][lr] = xv.w;
        float4 wv = *(const float4*)(W + (bn + lr)*256 + k0 + lc);
        sW[lc+0][lr] = wv.x; sW[lc+1][lr] = wv.y; sW[lc+2][lr] = wv.z; sW[lc+3][lr] = wv.w;
        __syncthreads();
#pragma unroll
        for (int k = 0; k < 16; k++) {
            float4 a = *(const float4*)&sX[k][tr];
            float4 b4 = *(const float4*)&sW[k][tc];
            float av[4] = {a.x, a.y, a.z, a.w};
            float bv[4] = {b4.x, b4.y, b4.z, b4.w};
#pragma unroll
            for (int i = 0; i < 4; i++)
#pragma unroll
                for (int j = 0; j < 4; j++) acc[i][j] += av[i] * bv[j];
        }
        __syncthreads();
    }
#pragma unroll
    for (int i = 0; i < 4; i++) {
        int r = bm + tr + i;
        if (r < N) {
#pragma unroll
            for (int j = 0; j < 4; j++)
                C[r*256 + bn + tc + j] = acc[i][j] + bias[bn + tc + j];
        }
    }
}

// ---------------- compound->protein attention (fused scores/softmax/PV/pool stats) ----------------
// grid (4 row-tiles, 256 batches), 256 threads
__global__ void att_cp(const int* __restrict__ comp_idx, const int* __restrict__ prot_idx,
                       const int* __restrict__ comp_lens, const int* __restrict__ prot_lens)
{
    extern __shared__ float smem[];
    float* q  = smem;              // 32*256
    float* s  = smem + 8192;       // 32*256
    float* kt = smem + 16384;      // 32*133 (reused as v-tile)
    const int b    = blockIdx.y;
    const int r0   = blockIdx.x * 32;
    const int tid  = threadIdx.x;
    const int lane = tid & 31;
    const int w    = tid >> 5;
    const int clen = comp_lens[b];
    const int plen = prot_lens[b];

    // load q rows (scaled by 1/sqrt(D)=1/16)
    for (int i = tid; i < 32*256; i += 256) {
        int r = i >> 8, d = i & 255;
        int gi = comp_idx[b*MCn + r0 + r];
        q[i] = g_cq[gi*256 + d] * 0.0625f;
    }
    __syncthreads();

    // scores: two 128-col halves, k-streamed
    for (int h = 0; h < 2; h++) {
        float acc[4][4] = {};
        for (int kc = 0; kc < 256; kc += 32) {
#pragma unroll
            for (int ii = 0; ii < 16; ii++) {
                int mloc = w*16 + ii;
                int gi = prot_idx[b*MPn + h*128 + mloc];
                kt[lane*133 + mloc] = g_pk[gi*256 + kc + lane];
            }
            __syncthreads();
#pragma unroll
            for (int kk = 0; kk < 32; kk++) {
                float qv[4];
#pragma unroll
                for (int i = 0; i < 4; i++) qv[i] = q[(4*w + i)*256 + kc + kk];
#pragma unroll
                for (int j = 0; j < 4; j++) {
                    float kv = kt[kk*133 + lane + 32*j];
#pragma unroll
                    for (int i = 0; i < 4; i++) acc[i][j] += qv[i] * kv;
                }
            }
            __syncthreads();
        }
#pragma unroll
        for (int i = 0; i < 4; i++)
#pragma unroll
            for (int j = 0; j < 4; j++)
                s[(4*w + i)*256 + h*128 + lane + 32*j] = acc[i][j];
    }
    __syncthreads();

    // masked softmax per row, imp_c row max
#pragma unroll
    for (int i = 0; i < 4; i++) {
        int r = 4*w + i;
        bool rvalid = (r0 + r) < clen;
        float v[8];
        float mx = -3.4e38f;
#pragma unroll
        for (int jj = 0; jj < 8; jj++) {
            int m = lane + 32*jj;
            float sc = s[r*256 + m];
            if (!rvalid || m >= plen) sc = -1e9f;
            v[jj] = sc; mx = fmaxf(mx, sc);
        }
#pragma unroll
        for (int o = 16; o; o >>= 1) mx = fmaxf(mx, __shfl_xor_sync(0xffffffffu, mx, o));
        float sum = 0.f;
#pragma unroll
        for (int jj = 0; jj < 8; jj++) { v[jj] = __expf(v[jj] - mx); sum += v[jj]; }
#pragma unroll
        for (int o = 16; o; o >>= 1) sum += __shfl_xor_sync(0xffffffffu, sum, o);
        float inv = 1.0f / sum;
        float pmax = 0.f;
#pragma unroll
        for (int jj = 0; jj < 8; jj++) {
            float p = v[jj] * inv;
            s[r*256 + lane + 32*jj] = p;
            pmax = fmaxf(pmax, p);
        }
#pragma unroll
        for (int o = 16; o; o >>= 1) pmax = fmaxf(pmax, __shfl_xor_sync(0xffffffffu, pmax, o));
        if (lane == 0) g_impc[b*MCn + r0 + r] = pmax;
    }
    __syncthreads();

    // imp_p: column max over valid rows of this tile, one atomic per column
    {
        int nval = clen - r0; if (nval > 32) nval = 32;
        if (nval > 0) {
            float vmax = 0.f;
            for (int r = 0; r < nval; r++) vmax = fmaxf(vmax, s[r*256 + tid]);
            atomicMax((int*)&g_impp[b*MPn + tid], __float_as_int(vmax));  // probs >= 0
        }
    }

    // PV: comp_fused[32][256] = probs[32][256] @ gathered pv[256][256]
    for (int dh = 0; dh < 2; dh++) {
        float acc[4][4] = {};
        for (int m0 = 0; m0 < 256; m0 += 32) {
#pragma unroll
            for (int ii = 0; ii < 4; ii++) {
                int mloc = w*4 + ii;
                int gi = prot_idx[b*MPn + m0 + mloc];
                const float* src = g_pv + gi*256 + dh*128;
#pragma unroll
                for (int qd = 0; qd < 4; qd++)
                    kt[mloc*133 + lane + 32*qd] = src[lane + 32*qd];
            }
            __syncthreads();
#pragma unroll
            for (int kk = 0; kk < 32; kk++) {
                float pr[4];
#pragma unroll
                for (int i = 0; i < 4; i++) pr[i] = s[(4*w + i)*256 + m0 + kk];
#pragma unroll
                for (int j = 0; j < 4; j++) {
                    float vv = kt[kk*133 + lane + 32*j];
#pragma unroll
                    for (int i = 0; i < 4; i++) acc[i][j] += pr[i] * vv;
                }
            }
            __syncthreads();
        }
#pragma unroll
        for (int i = 0; i < 4; i++)
#pragma unroll
            for (int j = 0; j < 4; j++)
                g_cf[(b*MCn + r0 + 4*w + i)*256 + dh*128 + lane + 32*j] = acc[i][j];
    }
}

// ---------------- protein->compound attention ----------------
// grid (8 row-tiles, 256 batches), 256 threads
__global__ void att_pc(const int* __restrict__ comp_idx, const int* __restrict__ prot_idx,
                       const int* __restrict__ comp_lens, const int* __restrict__ prot_lens)
{
    extern __shared__ float smem[];
    float* q  = smem;               // 32*256
    float* s  = smem + 8192;        // 32*128
    float* kt = smem + 8192 + 4096; // 32*133
    const int b    = blockIdx.y;
    const int r0   = blockIdx.x * 32;     // protein row base
    const int tid  = threadIdx.x;
    const int lane = tid & 31;
    const int w    = tid >> 5;
    const int clen = comp_lens[b];
    const int plen = prot_lens[b];

    for (int i = tid; i < 32*256; i += 256) {
        int r = i >> 8, d = i & 255;
        int gi = prot_idx[b*MPn + r0 + r];
        q[i] = g_pq[gi*256 + d] * 0.0625f;
    }
    __syncthreads();

    // scores: 128 cols (compound), k-streamed
    {
        float acc[4][4] = {};
        for (int kc = 0; kc < 256; kc += 32) {
#pragma unroll
            for (int ii = 0; ii < 16; ii++) {
                int nloc = w*16 + ii;
                int gi = comp_idx[b*MCn + nloc];
                kt[lane*133 + nloc] = g_ck[gi*256 + kc + lane];
            }
            __syncthreads();
#pragma unroll
            for (int kk = 0; kk < 32; kk++) {
                float qv[4];
#pragma unroll
                for (int i = 0; i < 4; i++) qv[i] = q[(4*w + i)*256 + kc + kk];
#pragma unroll
                for (int j = 0; j < 4; j++) {
                    float kv = kt[kk*133 + lane + 32*j];
#pragma unroll
                    for (int i = 0; i < 4; i++) acc[i][j] += qv[i] * kv;
                }
            }
            __syncthreads();
        }
#pragma unroll
        for (int i = 0; i < 4; i++)
#pragma unroll
            for (int j = 0; j < 4; j++)
                s[(4*w + i)*128 + lane + 32*j] = acc[i][j];
    }
    __syncthreads();

    // masked softmax over 128 compound cols
#pragma unroll
    for (int i = 0; i < 4; i++) {
        int r = 4*w + i;
        bool rvalid = (r0 + r) < plen;
        float v[4];
        float mx = -3.4e38f;
#pragma unroll
        for (int jj = 0; jj < 4; jj++) {
            int n = lane + 32*jj;
            float sc = s[r*128 + n];
            if (!rvalid || n >= clen) sc = -1e9f;
            v[jj] = sc; mx = fmaxf(mx, sc);
        }
#pragma unroll
        for (int o = 16; o; o >>= 1) mx = fmaxf(mx, __shfl_xor_sync(0xffffffffu, mx, o));
        float sum = 0.f;
#pragma unroll
        for (int jj = 0; jj < 4; jj++) { v[jj] = __expf(v[jj] - mx); sum += v[jj]; }
#pragma unroll
        for (int o = 16; o; o >>= 1) sum += __shfl_xor_sync(0xffffffffu, sum, o);
        float inv = 1.0f / sum;
#pragma unroll
        for (int jj = 0; jj < 4; jj++)
            s[r*128 + lane + 32*jj] = v[jj] * inv;
    }
    __syncthreads();

    // PV: prot_fused[32][256] = probs[32][128] @ gathered cv[128][256]
    for (int dh = 0; dh < 2; dh++) {
        float acc[4][4] = {};
        for (int m0 = 0; m0 < 128; m0 += 32) {
#pragma unroll
            for (int ii = 0; ii < 4; ii++) {
                int nloc = w*4 + ii;
                int gi = comp_idx[b*MCn + m0 + nloc];
                const float* src = g_cv + gi*256 + dh*128;
#pragma unroll
                for (int qd = 0; qd < 4; qd++)
                    kt[nloc*133 + lane + 32*qd] = src[lane + 32*qd];
            }
            __syncthreads();
#pragma unroll
            for (int kk = 0; kk < 32; kk++) {
                float pr[4];
#pragma unroll
                for (int i = 0; i < 4; i++) pr[i] = s[(4*w + i)*128 + m0 + kk];
#pragma unroll
                for (int j = 0; j < 4; j++) {
                    float vv = kt[kk*133 + lane + 32*j];
#pragma unroll
                    for (int i = 0; i < 4; i++) acc[i][j] += pr[i] * vv;
                }
            }
            __syncthreads();
        }
#pragma unroll
        for (int i = 0; i < 4; i++)
#pragma unroll
            for (int j = 0; j < 4; j++)
                g_pf[(b*MPn + r0 + 4*w + i)*256 + dh*128 + lane + 32*j] = acc[i][j];
    }
}

// ---------------- block reductions ----------------
__device__ __forceinline__ float blkMax(float v, float* red) {
#pragma unroll
    for (int o = 16; o; o >>= 1) v = fmaxf(v, __shfl_xor_sync(0xffffffffu, v, o));
    int w = threadIdx.x >> 5, l = threadIdx.x & 31;
    if (l == 0) red[w] = v;
    __syncthreads();
    if (threadIdx.x < 8) {
        float x = red[threadIdx.x];
#pragma unroll
        for (int o = 4; o; o >>= 1) x = fmaxf(x, __shfl_xor_sync(0x000000ffu, x, o));
        if (threadIdx.x == 0) red[0] = x;
    }
    __syncthreads();
    float r = red[0];
    __syncthreads();
    return r;
}

__device__ __forceinline__ float blkSum(float v, float* red) {
#pragma unroll
    for (int o = 16; o; o >>= 1) v += __shfl_xor_sync(0xffffffffu, v, o);
    int w = threadIdx.x >> 5, l = threadIdx.x & 31;
    if (l == 0) red[w] = v;
    __syncthreads();
    if (threadIdx.x < 8) {
        float x = red[threadIdx.x];
#pragma unroll
        for (int o = 4; o; o >>= 1) x += __shfl_xor_sync(0x000000ffu, x, o);
        if (threadIdx.x == 0) red[0] = x;
    }
    __syncthreads();
    float r = red[0];
    __syncthreads();
    return r;
}

// ---------------- finalize: pooling softmaxes + gating + weighted sums + logit ----------------
__global__ void finalize_k(const int* __restrict__ comp_lens, const int* __restrict__ prot_lens,
                           float* __restrict__ out)
{
    __shared__ float wc[128];
    __shared__ float wp[256];
    __shared__ float red[32];
    const int b = blockIdx.x, t = threadIdx.x;
    const int clen = comp_lens[b], plen = prot_lens[b];

    // w_c over 128 compound positions
    float x = -1e30f;
    if (t < 128 && t < clen) x = g_impc[b*MCn + t];
    float mx = blkMax(x, red);
    float e = (t < 128) ? __expf(x - mx) : 0.f;
    float sm = blkSum(e, red);
    if (t < 128) wc[t] = e / sm;

    // w_p over 256 protein positions
    float x2 = (t < plen) ? g_impp[b*MPn + t] : -1e30f;
    float mx2 = blkMax(x2, red);
    float e2 = __expf(x2 - mx2);
    float sm2 = blkSum(e2, red);
    wp[t] = e2 / sm2;
    __syncthreads();

    // herb_vec[t]: thread owns feature dim t
    float h = 0.f;
    for (int n = 0; n < clen; n++) {
        int off = (b*MCn + n)*256 + t;
        float g = g_gc[off];
        h += wc[n] * g_cf[off] * (1.0f / (1.0f + __expf(-g)));
    }
    float dd = 0.f;
    for (int m = 0; m < plen; m++) {
        int off = (b*MPn + m)*256 + t;
        float g = g_gp[off];
        dd += wp[m] * g_pf[off] * (1.0f / (1.0f + __expf(-g)));
    }
    float logit = blkSum(h * dd, red);
    if (t == 0) out[b] = 1.0f / (1.0f + __expf(-logit));
}

// ---------------- host launch ----------------
extern "C" void kernel_launch(void* const* d_in, const int* in_sizes, int n_in,
                              void* d_out, int out_size)
{
    const float* comp_emb = (const float*)d_in[0];
    const float* prot_emb = (const float*)d_in[1];
    const float* Wq_c = (const float*)d_in[2];  const float* bq_c = (const float*)d_in[3];
    const float* Wk_c = (const float*)d_in[4];  const float* bk_c = (const float*)d_in[5];
    const float* Wv_c = (const float*)d_in[6];  const float* bv_c = (const float*)d_in[7];
    const float* Wq_p = (const float*)d_in[8];  const float* bq_p = (const float*)d_in[9];
    const float* Wk_p = (const float*)d_in[10]; const float* bk_p = (const float*)d_in[11];
    const float* Wv_p = (const float*)d_in[12]; const float* bv_p = (const float*)d_in[13];
    const float* Wg_c = (const float*)d_in[14]; const float* bg_c = (const float*)d_in[15];
    const float* Wg_p = (const float*)d_in[16]; const float* bg_p = (const float*)d_in[17];
    const int* comp_idx  = (const int*)d_in[18];
    const int* prot_idx  = (const int*)d_in[19];
    const int* comp_lens = (const int*)d_in[20];
    const int* prot_lens = (const int*)d_in[21];
    float* out = (float*)d_out;

    const int NC = in_sizes[0] / 256;
    const int NP = in_sizes[1] / 256;

    float *p_cq, *p_ck, *p_cv, *p_pq, *p_pk, *p_pv, *p_cf, *p_pf, *p_gc, *p_gp;
    cudaGetSymbolAddress((void**)&p_cq, g_cq);
    cudaGetSymbolAddress((void**)&p_ck, g_ck);
    cudaGetSymbolAddress((void**)&p_cv, g_cv);
    cudaGetSymbolAddress((void**)&p_pq, g_pq);
    cudaGetSymbolAddress((void**)&p_pk, g_pk);
    cudaGetSymbolAddress((void**)&p_pv, g_pv);
    cudaGetSymbolAddress((void**)&p_cf, g_cf);
    cudaGetSymbolAddress((void**)&p_pf, g_pf);
    cudaGetSymbolAddress((void**)&p_gc, g_gc);
    cudaGetSymbolAddress((void**)&p_gp, g_gp);

    const int SMEM_CP = (32*256*2 + 32*133) * 4;   // 82560 B
    const int SMEM_PC = (32*256 + 32*128 + 32*133) * 4; // 66176 B
    cudaFuncSetAttribute(att_cp, cudaFuncAttributeMaxDynamicSharedMemorySize, SMEM_CP);
    cudaFuncSetAttribute(att_pc, cudaFuncAttributeMaxDynamicSharedMemorySize, SMEM_PC);

    init_impp_k<<<64, 1024>>>();

    dim3 gc(4, (NC + 63) / 64);
    dim3 gp(4, (NP + 63) / 64);
    gemm_nt<<<gc, 256>>>(comp_emb, Wq_c, bq_c, p_cq, NC);
    gemm_nt<<<gc, 256>>>(comp_emb, Wk_c, bk_c, p_ck, NC);
    gemm_nt<<<gc, 256>>>(comp_emb, Wv_c, bv_c, p_cv, NC);
    gemm_nt<<<gp, 256>>>(prot_emb, Wq_p, bq_p, p_pq, NP);
    gemm_nt<<<gp, 256>>>(prot_emb, Wk_p, bk_p, p_pk, NP);
    gemm_nt<<<gp, 256>>>(prot_emb, Wv_p, bv_p, p_pv, NP);

    att_cp<<<dim3(4, BATCH), 256, SMEM_CP>>>(comp_idx, prot_idx, comp_lens, prot_lens);
    att_pc<<<dim3(8, BATCH), 256, SMEM_PC>>>(comp_idx, prot_idx, comp_lens, prot_lens);

    gemm_nt<<<dim3(4, (BATCH*MCn) / 64), 256>>>(p_cf, Wg_c, bg_c, p_gc, BATCH*MCn);
    gemm_nt<<<dim3(4, (BATCH*MPn) / 64), 256>>>(p_pf, Wg_p, bg_p, p_gp, BATCH*MPn);

    finalize_k<<<BATCH, 256>>>(comp_lens, prot_lens, out);
}

// round 3
// speedup vs baseline: 1.1542x; 1.1542x over previous
#include <cuda_runtime.h>

#define DIM   256
#define BATCH 256
#define MCn   128
#define MPn   256
#define NMAX  20000

// ---------------- static device scratch ----------------
__device__ float g_cq[NMAX*DIM];
__device__ float g_ck[NMAX*DIM];
__device__ float g_cv[NMAX*DIM];
__device__ float g_pq[NMAX*DIM];
__device__ float g_pk[NMAX*DIM];
__device__ float g_pv[NMAX*DIM];
__device__ float g_cf[BATCH*MCn*DIM];   // comp_fused (pre-gate)
__device__ float g_pf[BATCH*MPn*DIM];   // prot_fused (pre-gate)
__device__ float g_gc[BATCH*MCn*DIM];   // gated comp_fused
__device__ float g_gp[BATCH*MPn*DIM];   // gated prot_fused
__device__ float g_impc[BATCH*MCn];
__device__ float g_impp[BATCH*MPn];

__global__ void init_impp_k() {
    int i = blockIdx.x * blockDim.x + threadIdx.x;
    if (i < BATCH*MPn) g_impp[i] = 0.0f;
}

// ---------------- SGEMM 128x128 tile, 8x8 micro: C = X @ W^T (+bias | gated) ----------------
// GATED=0: Out = X@W^T + bias.  GATED=1: Out = X * sigmoid(X@W^T + bias), with
// per-sequence length skipping (SEQ = padded seq length, lens per batch).
template<int GATED, int SEQ>
__global__ void __launch_bounds__(256, 2)
gemm128(const float* __restrict__ X, const float* __restrict__ W,
        const float* __restrict__ bias, float* __restrict__ Out,
        int M, const int* __restrict__ lens)
{
    __shared__ float sX[16][132];
    __shared__ float sW[16][132];
    const int tid = threadIdx.x;
    const int bm = blockIdx.y * 128;
    const int bn = blockIdx.x * 128;
    int lenloc = 1 << 30;
    if (GATED) {
        int b  = bm / SEQ;
        int n0 = bm - b * SEQ;
        lenloc = lens[b] - n0;
        if (lenloc <= 0) return;           // whole 128-row block is padding
    }
    const int ty = tid >> 4, tx = tid & 15;
    const bool wvalid = (!GATED) || (((tid >> 5) * 16) < lenloc);  // warp rows 16w..16w+15
    const int lrow = tid & 127;
    const int lkq  = (tid >> 7) * 8;       // k-offset 0 or 8 within 16-chunk
    const float* xsrc = X + (size_t)(bm + lrow) * 256 + lkq;
    const float* wsrc = W + (size_t)(bn + lrow) * 256 + lkq;
    const bool xrv = (bm + lrow) < M;

    float4 rx[2], rw[2];
#pragma unroll
    for (int j = 0; j < 2; j++) {
        rx[j] = xrv ? *(const float4*)(xsrc + 4*j) : make_float4(0.f,0.f,0.f,0.f);
        rw[j] = *(const float4*)(wsrc + 4*j);
    }
    float acc[8][8] = {};
    for (int s = 0; s < 16; s++) {
        __syncthreads();
#pragma unroll
        for (int j = 0; j < 2; j++) {
            int kb = lkq + 4*j;
            sX[kb+0][lrow] = rx[j].x; sX[kb+1][lrow] = rx[j].y;
            sX[kb+2][lrow] = rx[j].z; sX[kb+3][lrow] = rx[j].w;
            sW[kb+0][lrow] = rw[j].x; sW[kb+1][lrow] = rw[j].y;
            sW[kb+2][lrow] = rw[j].z; sW[kb+3][lrow] = rw[j].w;
        }
        __syncthreads();
        if (s < 15) {
            const float* xs = xsrc + (s+1)*16;
            const float* ws = wsrc + (s+1)*16;
#pragma unroll
            for (int j = 0; j < 2; j++) {
                rx[j] = xrv ? *(const float4*)(xs + 4*j) : make_float4(0.f,0.f,0.f,0.f);
                rw[j] = *(const float4*)(ws + 4*j);
            }
        }
        if (wvalid) {
#pragma unroll 4
            for (int k = 0; k < 16; k++) {
                float4 a0 = *(const float4*)&sX[k][ty*8];
                float4 a1 = *(const float4*)&sX[k][ty*8+4];
                float4 b0 = *(const float4*)&sW[k][tx*8];
                float4 b1 = *(const float4*)&sW[k][tx*8+4];
                float av[8] = {a0.x,a0.y,a0.z,a0.w,a1.x,a1.y,a1.z,a1.w};
                float bv[8] = {b0.x,b0.y,b0.z,b0.w,b1.x,b1.y,b1.z,b1.w};
#pragma unroll
                for (int i = 0; i < 8; i++)
#pragma unroll
                    for (int jj = 0; jj < 8; jj++)
                        acc[i][jj] += av[i] * bv[jj];
            }
        }
    }
    if (!wvalid) return;
    float4 bb0 = *(const float4*)(bias + bn + tx*8);
    float4 bb1 = *(const float4*)(bias + bn + tx*8 + 4);
    float bvv[8] = {bb0.x,bb0.y,bb0.z,bb0.w,bb1.x,bb1.y,bb1.z,bb1.w};
#pragma unroll
    for (int i = 0; i < 8; i++) {
        int r = bm + ty*8 + i;
        if (r < M) {
            float o[8];
            if (GATED) {
                const float* xr = X + (size_t)r*256 + bn + tx*8;
#pragma unroll
                for (int jj = 0; jj < 8; jj++) {
                    float logit = acc[i][jj] + bvv[jj];
                    o[jj] = xr[jj] * (1.0f / (1.0f + __expf(-logit)));
                }
            } else {
#pragma unroll
                for (int jj = 0; jj < 8; jj++) o[jj] = acc[i][jj] + bvv[jj];
            }
            float4* dst = (float4*)(Out + (size_t)r*256 + bn + tx*8);
            dst[0] = make_float4(o[0],o[1],o[2],o[3]);
            dst[1] = make_float4(o[4],o[5],o[6],o[7]);
        }
    }
}

// ---------------- compound->protein attention ----------------
__global__ void __launch_bounds__(256)
att_cp(const int* __restrict__ comp_idx, const int* __restrict__ prot_idx,
       const int* __restrict__ comp_lens, const int* __restrict__ prot_lens)
{
    extern __shared__ float smem[];
    float* q  = smem;              // 32*256
    float* s  = smem + 8192;       // 32*256
    float* kt = smem + 16384;      // 32*133
    const int b    = blockIdx.y;
    const int r0   = blockIdx.x * 32;
    const int tid  = threadIdx.x;
    const int lane = tid & 31;
    const int w    = tid >> 5;
    const int clen = comp_lens[b];
    const int plen = prot_lens[b];
    if (r0 >= clen) return;                    // fully padded row tile: outputs unread
    const int plen_c32 = (plen + 31) & ~31;

    for (int i = tid; i < 32*256; i += 256) {
        int r = i >> 8, d = i & 255;
        int gi = comp_idx[b*MCn + r0 + r];
        q[i] = g_cq[gi*256 + d] * 0.0625f;
    }
    __syncthreads();

    // scores (clamped to valid column chunks)
    for (int h = 0; h < 2; h++) {
        int mlim = plen_c32 - h*128;
        if (mlim <= 0) break;
        if (mlim > 128) mlim = 128;
        float acc[4][4] = {};
        for (int kc = 0; kc < 256; kc += 32) {
#pragma unroll
            for (int ii = 0; ii < 16; ii++) {
                int mloc = w*16 + ii;
                if (mloc < mlim) {
                    int gi = prot_idx[b*MPn + h*128 + mloc];
                    kt[lane*133 + mloc] = g_pk[gi*256 + kc + lane];
                }
            }
            __syncthreads();
#pragma unroll
            for (int kk = 0; kk < 32; kk++) {
                float qv[4];
#pragma unroll
                for (int i = 0; i < 4; i++) qv[i] = q[(4*w + i)*256 + kc + kk];
#pragma unroll
                for (int j = 0; j < 4; j++) {
                    if (32*j < mlim) {
                        float kv = kt[kk*133 + lane + 32*j];
#pragma unroll
                        for (int i = 0; i < 4; i++) acc[i][j] += qv[i] * kv;
                    }
                }
            }
            __syncthreads();
        }
#pragma unroll
        for (int i = 0; i < 4; i++)
#pragma unroll
            for (int j = 0; j < 4; j++)
                s[(4*w + i)*256 + h*128 + lane + 32*j] = acc[i][j];
    }
    __syncthreads();

    // masked softmax per row, imp_c row max
#pragma unroll
    for (int i = 0; i < 4; i++) {
        int r = 4*w + i;
        bool rvalid = (r0 + r) < clen;
        float v[8];
        float mx = -3.4e38f;
#pragma unroll
        for (int jj = 0; jj < 8; jj++) {
            int m = lane + 32*jj;
            float sc = s[r*256 + m];
            if (!rvalid || m >= plen) sc = -1e9f;
            v[jj] = sc; mx = fmaxf(mx, sc);
        }
#pragma unroll
        for (int o = 16; o; o >>= 1) mx = fmaxf(mx, __shfl_xor_sync(0xffffffffu, mx, o));
        float sum = 0.f;
#pragma unroll
        for (int jj = 0; jj < 8; jj++) { v[jj] = __expf(v[jj] - mx); sum += v[jj]; }
#pragma unroll
        for (int o = 16; o; o >>= 1) sum += __shfl_xor_sync(0xffffffffu, sum, o);
        float inv = 1.0f / sum;
        float pmax = 0.f;
#pragma unroll
        for (int jj = 0; jj < 8; jj++) {
            float p = v[jj] * inv;
            s[r*256 + lane + 32*jj] = p;
            pmax = fmaxf(pmax, p);
        }
#pragma unroll
        for (int o = 16; o; o >>= 1) pmax = fmaxf(pmax, __shfl_xor_sync(0xffffffffu, pmax, o));
        if (lane == 0) g_impc[b*MCn + r0 + r] = pmax;
    }
    __syncthreads();

    // imp_p column max over valid rows
    {
        int nval = clen - r0; if (nval > 32) nval = 32;
        float vmax = 0.f;
        for (int r = 0; r < nval; r++) vmax = fmaxf(vmax, s[r*256 + tid]);
        atomicMax((int*)&g_impp[b*MPn + tid], __float_as_int(vmax));
    }

    // PV (only valid column chunks)
    for (int dh = 0; dh < 2; dh++) {
        float acc[4][4] = {};
        for (int m0 = 0; m0 < plen_c32; m0 += 32) {
#pragma unroll
            for (int ii = 0; ii < 4; ii++) {
                int mloc = w*4 + ii;
                int gi = prot_idx[b*MPn + m0 + mloc];
                const float* src = g_pv + gi*256 + dh*128;
#pragma unroll
                for (int qd = 0; qd < 4; qd++)
                    kt[mloc*133 + lane + 32*qd] = src[lane + 32*qd];
            }
            __syncthreads();
#pragma unroll
            for (int kk = 0; kk < 32; kk++) {
                float pr[4];
#pragma unroll
                for (int i = 0; i < 4; i++) pr[i] = s[(4*w + i)*256 + m0 + kk];
#pragma unroll
                for (int j = 0; j < 4; j++) {
                    float vv = kt[kk*133 + lane + 32*j];
#pragma unroll
                    for (int i = 0; i < 4; i++) acc[i][j] += pr[i] * vv;
                }
            }
            __syncthreads();
        }
#pragma unroll
        for (int i = 0; i < 4; i++)
#pragma unroll
            for (int j = 0; j < 4; j++)
                g_cf[(b*MCn + r0 + 4*w + i)*256 + dh*128 + lane + 32*j] = acc[i][j];
    }
}

// ---------------- protein->compound attention ----------------
__global__ void __launch_bounds__(256)
att_pc(const int* __restrict__ comp_idx, const int* __restrict__ prot_idx,
       const int* __restrict__ comp_lens, const int* __restrict__ prot_lens)
{
    extern __shared__ float smem[];
    float* q  = smem;               // 32*256
    float* s  = smem + 8192;        // 32*128
    float* kt = smem + 8192 + 4096; // 32*133
    const int b    = blockIdx.y;
    const int r0   = blockIdx.x * 32;
    const int tid  = threadIdx.x;
    const int lane = tid & 31;
    const int w    = tid >> 5;
    const int clen = comp_lens[b];
    const int plen = prot_lens[b];
    if (r0 >= plen) return;
    const int clen_c32 = (clen + 31) & ~31;

    for (int i = tid; i < 32*256; i += 256) {
        int r = i >> 8, d = i & 255;
        int gi = prot_idx[b*MPn + r0 + r];
        q[i] = g_pq[gi*256 + d] * 0.0625f;
    }
    __syncthreads();

    // scores over compound cols (clamped)
    {
        float acc[4][4] = {};
        for (int kc = 0; kc < 256; kc += 32) {
#pragma unroll
            for (int ii = 0; ii < 16; ii++) {
                int nloc = w*16 + ii;
                if (nloc < clen_c32) {
                    int gi = comp_idx[b*MCn + nloc];
                    kt[lane*133 + nloc] = g_ck[gi*256 + kc + lane];
                }
            }
            __syncthreads();
#pragma unroll
            for (int kk = 0; kk < 32; kk++) {
                float qv[4];
#pragma unroll
                for (int i = 0; i < 4; i++) qv[i] = q[(4*w + i)*256 + kc + kk];
#pragma unroll
                for (int j = 0; j < 4; j++) {
                    if (32*j < clen_c32) {
                        float kv = kt[kk*133 + lane + 32*j];
#pragma unroll
                        for (int i = 0; i < 4; i++) acc[i][j] += qv[i] * kv;
                    }
                }
            }
            __syncthreads();
        }
#pragma unroll
        for (int i = 0; i < 4; i++)
#pragma unroll
            for (int j = 0; j < 4; j++)
                s[(4*w + i)*128 + lane + 32*j] = acc[i][j];
    }
    __syncthreads();

    // masked softmax over 128 compound cols
#pragma unroll
    for (int i = 0; i < 4; i++) {
        int r = 4*w + i;
        bool rvalid = (r0 + r) < plen;
        float v[4];
        float mx = -3.4e38f;
#pragma unroll
        for (int jj = 0; jj < 4; jj++) {
            int n = lane + 32*jj;
            float sc = s[r*128 + n];
            if (!rvalid || n >= clen) sc = -1e9f;
            v[jj] = sc; mx = fmaxf(mx, sc);
        }
#pragma unroll
        for (int o = 16; o; o >>= 1) mx = fmaxf(mx, __shfl_xor_sync(0xffffffffu, mx, o));
        float sum = 0.f;
#pragma unroll
        for (int jj = 0; jj < 4; jj++) { v[jj] = __expf(v[jj] - mx); sum += v[jj]; }
#pragma unroll
        for (int o = 16; o; o >>= 1) sum += __shfl_xor_sync(0xffffffffu, sum, o);
        float inv = 1.0f / sum;
#pragma unroll
        for (int jj = 0; jj < 4; jj++)
            s[r*128 + lane + 32*jj] = v[jj] * inv;
    }
    __syncthreads();

    // PV (clamped)
    for (int dh = 0; dh < 2; dh++) {
        float acc[4][4] = {};
        for (int m0 = 0; m0 < clen_c32; m0 += 32) {
#pragma unroll
            for (int ii = 0; ii < 4; ii++) {
                int nloc = w*4 + ii;
                int gi = comp_idx[b*MCn + m0 + nloc];
                const float* src = g_cv + gi*256 + dh*128;
#pragma unroll
                for (int qd = 0; qd < 4; qd++)
                    kt[nloc*133 + lane + 32*qd] = src[lane + 32*qd];
            }
            __syncthreads();
#pragma unroll
            for (int kk = 0; kk < 32; kk++) {
                float pr[4];
#pragma unroll
                for (int i = 0; i < 4; i++) pr[i] = s[(4*w + i)*128 + m0 + kk];
#pragma unroll
                for (int j = 0; j < 4; j++) {
                    float vv = kt[kk*133 + lane + 32*j];
#pragma unroll
                    for (int i = 0; i < 4; i++) acc[i][j] += pr[i] * vv;
                }
            }
            __syncthreads();
        }
#pragma unroll
        for (int i = 0; i < 4; i++)
#pragma unroll
            for (int j = 0; j < 4; j++)
                g_pf[(b*MPn + r0 + 4*w + i)*256 + dh*128 + lane + 32*j] = acc[i][j];
    }
}

// ---------------- block reductions ----------------
__device__ __forceinline__ float blkMax(float v, float* red) {
#pragma unroll
    for (int o = 16; o; o >>= 1) v = fmaxf(v, __shfl_xor_sync(0xffffffffu, v, o));
    int w = threadIdx.x >> 5, l = threadIdx.x & 31;
    if (l == 0) red[w] = v;
    __syncthreads();
    if (threadIdx.x < 8) {
        float x = red[threadIdx.x];
#pragma unroll
        for (int o = 4; o; o >>= 1) x = fmaxf(x, __shfl_xor_sync(0x000000ffu, x, o));
        if (threadIdx.x == 0) red[0] = x;
    }
    __syncthreads();
    float r = red[0];
    __syncthreads();
    return r;
}

__device__ __forceinline__ float blkSum(float v, float* red) {
#pragma unroll
    for (int o = 16; o; o >>= 1) v += __shfl_xor_sync(0xffffffffu, v, o);
    int w = threadIdx.x >> 5, l = threadIdx.x & 31;
    if (l == 0) red[w] = v;
    __syncthreads();
    if (threadIdx.x < 8) {
        float x = red[threadIdx.x];
#pragma unroll
        for (int o = 4; o; o >>= 1) x += __shfl_xor_sync(0x000000ffu, x, o);
        if (threadIdx.x == 0) red[0] = x;
    }
    __syncthreads();
    float r = red[0];
    __syncthreads();
    return r;
}

// ---------------- finalize ----------------
__global__ void __launch_bounds__(256)
finalize_k(const int* __restrict__ comp_lens, const int* __restrict__ prot_lens,
           float* __restrict__ out)
{
    __shared__ float wc[128];
    __shared__ float wp[256];
    __shared__ float red[32];
    const int b = blockIdx.x, t = threadIdx.x;
    const int clen = comp_lens[b], plen = prot_lens[b];

    float x = -1e30f;
    if (t < 128 && t < clen) x = g_impc[b*MCn + t];
    float mx = blkMax(x, red);
    float e = (t < 128) ? __expf(x - mx) : 0.f;
    float sm = blkSum(e, red);
    if (t < 128) wc[t] = e / sm;

    float x2 = (t < plen) ? g_impp[b*MPn + t] : -1e30f;
    float mx2 = blkMax(x2, red);
    float e2 = __expf(x2 - mx2);
    float sm2 = blkSum(e2, red);
    wp[t] = e2 / sm2;
    __syncthreads();

    float h = 0.f;
    for (int n = 0; n < clen; n++)
        h += wc[n] * g_gc[(b*MCn + n)*256 + t];
    float dd = 0.f;
    for (int m = 0; m < plen; m++)
        dd += wp[m] * g_gp[(b*MPn + m)*256 + t];
    float logit = blkSum(h * dd, red);
    if (t == 0) out[b] = 1.0f / (1.0f + __expf(-logit));
}

// ---------------- host launch ----------------
extern "C" void kernel_launch(void* const* d_in, const int* in_sizes, int n_in,
                              void* d_out, int out_size)
{
    const float* comp_emb = (const float*)d_in[0];
    const float* prot_emb = (const float*)d_in[1];
    const float* Wq_c = (const float*)d_in[2];  const float* bq_c = (const float*)d_in[3];
    const float* Wk_c = (const float*)d_in[4];  const float* bk_c = (const float*)d_in[5];
    const float* Wv_c = (const float*)d_in[6];  const float* bv_c = (const float*)d_in[7];
    const float* Wq_p = (const float*)d_in[8];  const float* bq_p = (const float*)d_in[9];
    const float* Wk_p = (const float*)d_in[10]; const float* bk_p = (const float*)d_in[11];
    const float* Wv_p = (const float*)d_in[12]; const float* bv_p = (const float*)d_in[13];
    const float* Wg_c = (const float*)d_in[14]; const float* bg_c = (const float*)d_in[15];
    const float* Wg_p = (const float*)d_in[16]; const float* bg_p = (const float*)d_in[17];
    const int* comp_idx  = (const int*)d_in[18];
    const int* prot_idx  = (const int*)d_in[19];
    const int* comp_lens = (const int*)d_in[20];
    const int* prot_lens = (const int*)d_in[21];
    float* out = (float*)d_out;

    const int NC = in_sizes[0] / 256;
    const int NP = in_sizes[1] / 256;

    float *p_cq, *p_ck, *p_cv, *p_pq, *p_pk, *p_pv, *p_cf, *p_pf, *p_gc, *p_gp;
    cudaGetSymbolAddress((void**)&p_cq, g_cq);
    cudaGetSymbolAddress((void**)&p_ck, g_ck);
    cudaGetSymbolAddress((void**)&p_cv, g_cv);
    cudaGetSymbolAddress((void**)&p_pq, g_pq);
    cudaGetSymbolAddress((void**)&p_pk, g_pk);
    cudaGetSymbolAddress((void**)&p_pv, g_pv);
    cudaGetSymbolAddress((void**)&p_cf, g_cf);
    cudaGetSymbolAddress((void**)&p_pf, g_pf);
    cudaGetSymbolAddress((void**)&p_gc, g_gc);
    cudaGetSymbolAddress((void**)&p_gp, g_gp);

    const int SMEM_CP = (32*256*2 + 32*133) * 4;
    const int SMEM_PC = (32*256 + 32*128 + 32*133) * 4;
    cudaFuncSetAttribute(att_cp, cudaFuncAttributeMaxDynamicSharedMemorySize, SMEM_CP);
    cudaFuncSetAttribute(att_pc, cudaFuncAttributeMaxDynamicSharedMemorySize, SMEM_PC);

    init_impp_k<<<64, 1024>>>();

    dim3 gc(2, (NC + 127) / 128);
    dim3 gp(2, (NP + 127) / 128);
    gemm128<0,1><<<gc, 256>>>(comp_emb, Wq_c, bq_c, p_cq, NC, nullptr);
    gemm128<0,1><<<gc, 256>>>(comp_emb, Wk_c, bk_c, p_ck, NC, nullptr);
    gemm128<0,1><<<gc, 256>>>(comp_emb, Wv_c, bv_c, p_cv, NC, nullptr);
    gemm128<0,1><<<gp, 256>>>(prot_emb, Wq_p, bq_p, p_pq, NP, nullptr);
    gemm128<0,1><<<gp, 256>>>(prot_emb, Wk_p, bk_p, p_pk, NP, nullptr);
    gemm128<0,1><<<gp, 256>>>(prot_emb, Wv_p, bv_p, p_pv, NP, nullptr);

    att_cp<<<dim3(4, BATCH), 256, SMEM_CP>>>(comp_idx, prot_idx, comp_lens, prot_lens);
    att_pc<<<dim3(8, BATCH), 256, SMEM_PC>>>(comp_idx, prot_idx, comp_lens, prot_lens);

    gemm128<1,MCn><<<dim3(2, (BATCH*MCn)/128), 256>>>(p_cf, Wg_c, bg_c, p_gc, BATCH*MCn, comp_lens);
    gemm128<1,MPn><<<dim3(2, (BATCH*MPn)/128), 256>>>(p_pf, Wg_p, bg_p, p_gp, BATCH*MPn, prot_lens);

    finalize_k<<<BATCH, 256>>>(comp_lens, prot_lens, out);
}

// round 7
// speedup vs baseline: 1.5302x; 1.3258x over previous
#include <cuda_runtime.h>

#define DIM   256
#define BATCH 256
#define MCn   128
#define MPn   256
#define NMAX  20000

// ---------------- static device scratch ----------------
__device__ float g_cq[NMAX*DIM];
__device__ float g_ck[NMAX*DIM];
__device__ float g_cv[NMAX*DIM];
__device__ float g_pq[NMAX*DIM];
__device__ float g_pk[NMAX*DIM];
__device__ float g_pv[NMAX*DIM];
__device__ float g_cf[BATCH*MCn*DIM];   // comp_fused (pre-gate)
__device__ float g_pf[BATCH*MPn*DIM];   // prot_fused (pre-gate)
__device__ float g_gc[BATCH*MCn*DIM];   // gated comp_fused
__device__ float g_gp[BATCH*MPn*DIM];   // gated prot_fused
__device__ float g_impc[BATCH*MCn];
__device__ float g_impp[BATCH*MPn];

__global__ void init_impp_k() {
    int i = blockIdx.x * blockDim.x + threadIdx.x;
    if (i < BATCH*MPn) g_impp[i] = 0.0f;
}

// ---------------- projection GEMM: 3 outputs per launch ----------------
// Tile 128(M) x 64(N), 256 threads, 8x4 micro, double-buffered k-chunks of 16.
__global__ void __launch_bounds__(256, 3)
gemm3(const float* __restrict__ X,
      const float* __restrict__ W0, const float* __restrict__ bz0, float* __restrict__ O0,
      const float* __restrict__ W1, const float* __restrict__ bz1, float* __restrict__ O1,
      const float* __restrict__ W2, const float* __restrict__ bz2, float* __restrict__ O2,
      int M)
{
    __shared__ float sX[2][16][132];
    __shared__ float sW[2][16][68];
    const float* W; const float* bias; float* Out;
    if (blockIdx.z == 0)      { W = W0; bias = bz0; Out = O0; }
    else if (blockIdx.z == 1) { W = W1; bias = bz1; Out = O1; }
    else                      { W = W2; bias = bz2; Out = O2; }
    const int tid = threadIdx.x;
    const int bm = blockIdx.y * 128;
    const int bn = blockIdx.x * 64;
    const int ty = tid >> 4, tx = tid & 15;
    const int xr = tid >> 1, xk = (tid & 1) * 8;
    const int wr = tid & 63, wk = (tid >> 6) * 4;
    const float* xp = X + (size_t)(bm + xr) * 256 + xk;
    const float* wp = W + (size_t)(bn + wr) * 256 + wk;
    const bool xv = (bm + xr) < M;

    float4 rx0 = xv ? *(const float4*)xp       : make_float4(0.f,0.f,0.f,0.f);
    float4 rx1 = xv ? *(const float4*)(xp + 4) : make_float4(0.f,0.f,0.f,0.f);
    float4 rw0 = *(const float4*)wp;
    sX[0][xk+0][xr]=rx0.x; sX[0][xk+1][xr]=rx0.y; sX[0][xk+2][xr]=rx0.z; sX[0][xk+3][xr]=rx0.w;
    sX[0][xk+4][xr]=rx1.x; sX[0][xk+5][xr]=rx1.y; sX[0][xk+6][xr]=rx1.z; sX[0][xk+7][xr]=rx1.w;
    sW[0][wk+0][wr]=rw0.x; sW[0][wk+1][wr]=rw0.y; sW[0][wk+2][wr]=rw0.z; sW[0][wk+3][wr]=rw0.w;
    __syncthreads();

    float acc[8][4] = {};
#pragma unroll 1
    for (int s = 0; s < 16; s++) {
        const int cur = s & 1;
        if (s < 15) {
            const float* xq = xp + (s+1)*16;
            rx0 = xv ? *(const float4*)xq       : make_float4(0.f,0.f,0.f,0.f);
            rx1 = xv ? *(const float4*)(xq + 4) : make_float4(0.f,0.f,0.f,0.f);
            rw0 = *(const float4*)(wp + (s+1)*16);
        }
#pragma unroll
        for (int k = 0; k < 16; k++) {
            float4 a0 = *(const float4*)&sX[cur][k][ty*8];
            float4 a1 = *(const float4*)&sX[cur][k][ty*8+4];
            float4 bq = *(const float4*)&sW[cur][k][tx*4];
            float av[8] = {a0.x,a0.y,a0.z,a0.w,a1.x,a1.y,a1.z,a1.w};
            float bv[4] = {bq.x,bq.y,bq.z,bq.w};
#pragma unroll
            for (int i = 0; i < 8; i++)
#pragma unroll
                for (int j = 0; j < 4; j++) acc[i][j] += av[i]*bv[j];
        }
        if (s < 15) {
            const int nxt = cur ^ 1;
            sX[nxt][xk+0][xr]=rx0.x; sX[nxt][xk+1][xr]=rx0.y; sX[nxt][xk+2][xr]=rx0.z; sX[nxt][xk+3][xr]=rx0.w;
            sX[nxt][xk+4][xr]=rx1.x; sX[nxt][xk+5][xr]=rx1.y; sX[nxt][xk+6][xr]=rx1.z; sX[nxt][xk+7][xr]=rx1.w;
            sW[nxt][wk+0][wr]=rw0.x; sW[nxt][wk+1][wr]=rw0.y; sW[nxt][wk+2][wr]=rw0.z; sW[nxt][wk+3][wr]=rw0.w;
            __syncthreads();
        }
    }
    float4 bb = *(const float4*)(bias + bn + tx*4);
    float bvv[4] = {bb.x, bb.y, bb.z, bb.w};
#pragma unroll
    for (int i = 0; i < 8; i++) {
        int r = bm + ty*8 + i;
        if (r < M)
            *(float4*)(Out + (size_t)r*256 + bn + tx*4) =
                make_float4(acc[i][0]+bvv[0], acc[i][1]+bvv[1],
                            acc[i][2]+bvv[2], acc[i][3]+bvv[3]);
    }
}

// ---------------- gated GEMM: Out = X * sigmoid(X@W^T + b), length-skipped ----------------
template<int SEQ>
__global__ void __launch_bounds__(256, 3)
gemmg(const float* __restrict__ X, const float* __restrict__ W,
      const float* __restrict__ bias, float* __restrict__ Out,
      const int* __restrict__ lens)
{
    __shared__ float sX[2][16][132];
    __shared__ float sW[2][16][68];
    const int tid = threadIdx.x;
    const int bm = blockIdx.y * 128;
    const int bn = blockIdx.x * 64;
    const int b = bm / SEQ;
    const int lenloc = lens[b] - (bm - b*SEQ);
    if (lenloc <= 0) return;
    const bool wvalid = ((tid >> 5) * 16) < lenloc;   // warp rows 16w..16w+15
    const int ty = tid >> 4, tx = tid & 15;
    const int xr = tid >> 1, xk = (tid & 1) * 8;
    const int wr = tid & 63, wk = (tid >> 6) * 4;
    const float* xp = X + (size_t)(bm + xr) * 256 + xk;
    const float* wp = W + (size_t)(bn + wr) * 256 + wk;

    float4 rx0 = *(const float4*)xp;
    float4 rx1 = *(const float4*)(xp + 4);
    float4 rw0 = *(const float4*)wp;
    sX[0][xk+0][xr]=rx0.x; sX[0][xk+1][xr]=rx0.y; sX[0][xk+2][xr]=rx0.z; sX[0][xk+3][xr]=rx0.w;
    sX[0][xk+4][xr]=rx1.x; sX[0][xk+5][xr]=rx1.y; sX[0][xk+6][xr]=rx1.z; sX[0][xk+7][xr]=rx1.w;
    sW[0][wk+0][wr]=rw0.x; sW[0][wk+1][wr]=rw0.y; sW[0][wk+2][wr]=rw0.z; sW[0][wk+3][wr]=rw0.w;
    __syncthreads();

    float acc[8][4] = {};
#pragma unroll 1
    for (int s = 0; s < 16; s++) {
        const int cur = s & 1;
        if (s < 15) {
            const float* xq = xp + (s+1)*16;
            rx0 = *(const float4*)xq;
            rx1 = *(const float4*)(xq + 4);
            rw0 = *(const float4*)(wp + (s+1)*16);
        }
        if (wvalid) {
#pragma unroll
            for (int k = 0; k < 16; k++) {
                float4 a0 = *(const float4*)&sX[cur][k][ty*8];
                float4 a1 = *(const float4*)&sX[cur][k][ty*8+4];
                float4 bq = *(const float4*)&sW[cur][k][tx*4];
                float av[8] = {a0.x,a0.y,a0.z,a0.w,a1.x,a1.y,a1.z,a1.w};
                float bv[4] = {bq.x,bq.y,bq.z,bq.w};
#pragma unroll
                for (int i = 0; i < 8; i++)
#pragma unroll
                    for (int j = 0; j < 4; j++) acc[i][j] += av[i]*bv[j];
            }
        }
        if (s < 15) {
            const int nxt = cur ^ 1;
            sX[nxt][xk+0][xr]=rx0.x; sX[nxt][xk+1][xr]=rx0.y; sX[nxt][xk+2][xr]=rx0.z; sX[nxt][xk+3][xr]=rx0.w;
            sX[nxt][xk+4][xr]=rx1.x; sX[nxt][xk+5][xr]=rx1.y; sX[nxt][xk+6][xr]=rx1.z; sX[nxt][xk+7][xr]=rx1.w;
            sW[nxt][wk+0][wr]=rw0.x; sW[nxt][wk+1][wr]=rw0.y; sW[nxt][wk+2][wr]=rw0.z; sW[nxt][wk+3][wr]=rw0.w;
            __syncthreads();
        }
    }
    if (!wvalid) return;
    float4 bb = *(const float4*)(bias + bn + tx*4);
    float bvv[4] = {bb.x, bb.y, bb.z, bb.w};
#pragma unroll
    for (int i = 0; i < 8; i++) {
        int r = bm + ty*8 + i;
        float4 xr4 = *(const float4*)(X + (size_t)r*256 + bn + tx*4);
        float xa[4] = {xr4.x, xr4.y, xr4.z, xr4.w};
        float o[4];
#pragma unroll
        for (int j = 0; j < 4; j++) {
            float logit = acc[i][j] + bvv[j];
            o[j] = xa[j] * (1.0f / (1.0f + __expf(-logit)));
        }
        *(float4*)(Out + (size_t)r*256 + bn + tx*4) = make_float4(o[0],o[1],o[2],o[3]);
    }
}

// ---------------- compound->protein attention (k-vectorized) ----------------
// smem: q[32][260], s[32][256], kt[128][260]
__global__ void __launch_bounds__(256)
att_cp(const int* __restrict__ comp_idx, const int* __restrict__ prot_idx,
       const int* __restrict__ comp_lens, const int* __restrict__ prot_lens)
{
    extern __shared__ float smem[];
    float* q  = smem;                   // 32*260
    float* s  = smem + 32*260;          // 32*256
    float* kt = smem + 32*260 + 32*256; // 128*260
    const int b = blockIdx.y;
    const int r0 = blockIdx.x * 32;
    const int tid = threadIdx.x, lane = tid & 31, w = tid >> 5;
    const int clen = comp_lens[b], plen = prot_lens[b];
    if (r0 >= clen) return;

    // gather q rows (scaled by 1/16)
    for (int i = tid; i < 32*64; i += 256) {
        int row = i >> 6, kq = (i & 63) << 2;
        int gi = comp_idx[b*MCn + r0 + row];
        float4 v = *(const float4*)(g_cq + (size_t)gi*256 + kq);
        v.x *= 0.0625f; v.y *= 0.0625f; v.z *= 0.0625f; v.w *= 0.0625f;
        *(float4*)&q[row*260 + kq] = v;
    }
    __syncthreads();

    // scores in 128-col chunks
    for (int m0 = 0; m0 < plen; m0 += 128) {
        int mrows = plen - m0; if (mrows > 128) mrows = 128;
        int mr4 = (mrows + 3) & ~3;
        for (int i = tid; i < 128*64; i += 256) {
            int row = i >> 6;
            if (row < mr4) {
                int kq = (i & 63) << 2;
                int gi = prot_idx[b*MPn + m0 + row];
                *(float4*)&kt[row*260 + kq] = *(const float4*)(g_pk + (size_t)gi*256 + kq);
            }
        }
        __syncthreads();
        float acc[4][4] = {};
#pragma unroll 2
        for (int k = 0; k < 256; k += 4) {
            float4 qv[4];
#pragma unroll
            for (int i = 0; i < 4; i++) qv[i] = *(const float4*)&q[(4*w+i)*260 + k];
#pragma unroll
            for (int j = 0; j < 4; j++) {
                if (32*j < mrows) {
                    float4 kv = *(const float4*)&kt[(lane + 32*j)*260 + k];
#pragma unroll
                    for (int i = 0; i < 4; i++)
                        acc[i][j] += qv[i].x*kv.x + qv[i].y*kv.y + qv[i].z*kv.z + qv[i].w*kv.w;
                }
            }
        }
#pragma unroll
        for (int i = 0; i < 4; i++)
#pragma unroll
            for (int j = 0; j < 4; j++)
                s[(4*w+i)*256 + m0 + lane + 32*j] = acc[i][j];
        __syncthreads();
    }

    // masked softmax per row + imp_c
#pragma unroll
    for (int i = 0; i < 4; i++) {
        int r = 4*w + i;
        bool rvalid = (r0 + r) < clen;
        float v[8];
        float mx = -3.4e38f;
#pragma unroll
        for (int jj = 0; jj < 8; jj++) {
            int m = lane + 32*jj;
            float sc = s[r*256 + m];
            if (!rvalid || m >= plen) sc = -1e9f;
            v[jj] = sc; mx = fmaxf(mx, sc);
        }
#pragma unroll
        for (int o = 16; o; o >>= 1) mx = fmaxf(mx, __shfl_xor_sync(0xffffffffu, mx, o));
        float sum = 0.f;
#pragma unroll
        for (int jj = 0; jj < 8; jj++) { v[jj] = __expf(v[jj] - mx); sum += v[jj]; }
#pragma unroll
        for (int o = 16; o; o >>= 1) sum += __shfl_xor_sync(0xffffffffu, sum, o);
        float inv = 1.0f / sum;
        float pmax = 0.f;
#pragma unroll
        for (int jj = 0; jj < 8; jj++) {
            float p = v[jj] * inv;
            s[r*256 + lane + 32*jj] = p;
            pmax = fmaxf(pmax, p);
        }
#pragma unroll
        for (int o = 16; o; o >>= 1) pmax = fmaxf(pmax, __shfl_xor_sync(0xffffffffu, pmax, o));
        if (lane == 0) g_impc[b*MCn + r0 + r] = pmax;
    }
    __syncthreads();

    // imp_p column max over valid rows
    {
        int nval = clen - r0; if (nval > 32) nval = 32;
        float vmax = 0.f;
        for (int r = 0; r < nval; r++) vmax = fmaxf(vmax, s[r*256 + tid]);
        atomicMax((int*)&g_impp[b*MPn + tid], __float_as_int(vmax));
    }

    // PV in 128-col chunks, lane owns d = lane*4..+3 and 128+lane*4..+3
    float accO[4][8] = {};
    for (int c0 = 0; c0 < plen; c0 += 128) {
        int crows = plen - c0; if (crows > 128) crows = 128;
        int cr4 = (crows + 3) & ~3;
        __syncthreads();
        for (int i = tid; i < 128*64; i += 256) {
            int row = i >> 6;
            if (row < cr4) {
                int kq = (i & 63) << 2;
                int gi = prot_idx[b*MPn + c0 + row];
                *(float4*)&kt[row*260 + kq] = *(const float4*)(g_pv + (size_t)gi*256 + kq);
            }
        }
        __syncthreads();
#pragma unroll 2
        for (int c = 0; c < cr4; c += 4) {
            float pr[4][4];
#pragma unroll
            for (int i = 0; i < 4; i++) {
                float4 p = *(const float4*)&s[(4*w+i)*256 + c0 + c];
                pr[i][0]=p.x; pr[i][1]=p.y; pr[i][2]=p.z; pr[i][3]=p.w;
            }
#pragma unroll
            for (int cc = 0; cc < 4; cc++) {
                float4 v0 = *(const float4*)&kt[(c+cc)*260 + lane*4];
                float4 v1 = *(const float4*)&kt[(c+cc)*260 + 128 + lane*4];
#pragma unroll
                for (int i = 0; i < 4; i++) {
                    float p = pr[i][cc];
                    accO[i][0] += p*v0.x; accO[i][1] += p*v0.y;
                    accO[i][2] += p*v0.z; accO[i][3] += p*v0.w;
                    accO[i][4] += p*v1.x; accO[i][5] += p*v1.y;
                    accO[i][6] += p*v1.z; accO[i][7] += p*v1.w;
                }
            }
        }
    }
#pragma unroll
    for (int i = 0; i < 4; i++) {
        size_t base = (size_t)(b*MCn + r0 + 4*w + i)*256;
        *(float4*)(g_cf + base + lane*4)       = make_float4(accO[i][0],accO[i][1],accO[i][2],accO[i][3]);
        *(float4*)(g_cf + base + 128 + lane*4) = make_float4(accO[i][4],accO[i][5],accO[i][6],accO[i][7]);
    }
}

// ---------------- protein->compound attention (k-vectorized, single 128-col chunk) ----------------
// smem: q[32][260], s[32][128], kt[128][260]
__global__ void __launch_bounds__(256)
att_pc(const int* __restrict__ comp_idx, const int* __restrict__ prot_idx,
       const int* __restrict__ comp_lens, const int* __restrict__ prot_lens)
{
    extern __shared__ float smem[];
    float* q  = smem;                   // 32*260
    float* s  = smem + 32*260;          // 32*128
    float* kt = smem + 32*260 + 32*128; // 128*260
    const int b = blockIdx.y;
    const int r0 = blockIdx.x * 32;
    const int tid = threadIdx.x, lane = tid & 31, w = tid >> 5;
    const int clen = comp_lens[b], plen = prot_lens[b];
    if (r0 >= plen) return;
    const int cr4 = (clen + 3) & ~3;

    for (int i = tid; i < 32*64; i += 256) {
        int row = i >> 6, kq = (i & 63) << 2;
        int gi = prot_idx[b*MPn + r0 + row];
        float4 v = *(const float4*)(g_pq + (size_t)gi*256 + kq);
        v.x *= 0.0625f; v.y *= 0.0625f; v.z *= 0.0625f; v.w *= 0.0625f;
        *(float4*)&q[row*260 + kq] = v;
    }
    // K tile (compound rows)
    for (int i = tid; i < 128*64; i += 256) {
        int row = i >> 6;
        if (row < cr4) {
            int kq = (i & 63) << 2;
            int gi = comp_idx[b*MCn + row];
            *(float4*)&kt[row*260 + kq] = *(const float4*)(g_ck + (size_t)gi*256 + kq);
        }
    }
    __syncthreads();

    {
        float acc[4][4] = {};
#pragma unroll 2
        for (int k = 0; k < 256; k += 4) {
            float4 qv[4];
#pragma unroll
            for (int i = 0; i < 4; i++) qv[i] = *(const float4*)&q[(4*w+i)*260 + k];
#pragma unroll
            for (int j = 0; j < 4; j++) {
                if (32*j < clen) {
                    float4 kv = *(const float4*)&kt[(lane + 32*j)*260 + k];
#pragma unroll
                    for (int i = 0; i < 4; i++)
                        acc[i][j] += qv[i].x*kv.x + qv[i].y*kv.y + qv[i].z*kv.z + qv[i].w*kv.w;
                }
            }
        }
#pragma unroll
        for (int i = 0; i < 4; i++)
#pragma unroll
            for (int j = 0; j < 4; j++)
                s[(4*w+i)*128 + lane + 32*j] = acc[i][j];
    }

    // masked softmax over 128 compound cols (per-warp rows; s rows read by same warp only)
#pragma unroll
    for (int i = 0; i < 4; i++) {
        int r = 4*w + i;
        bool rvalid = (r0 + r) < plen;
        float v[4];
        float mx = -3.4e38f;
#pragma unroll
        for (int jj = 0; jj < 4; jj++) {
            int n = lane + 32*jj;
            float sc = s[r*128 + n];
            if (!rvalid || n >= clen) sc = -1e9f;
            v[jj] = sc; mx = fmaxf(mx, sc);
        }
#pragma unroll
        for (int o = 16; o; o >>= 1) mx = fmaxf(mx, __shfl_xor_sync(0xffffffffu, mx, o));
        float sum = 0.f;
#pragma unroll
        for (int jj = 0; jj < 4; jj++) { v[jj] = __expf(v[jj] - mx); sum += v[jj]; }
#pragma unroll
        for (int o = 16; o; o >>= 1) sum += __shfl_xor_sync(0xffffffffu, sum, o);
        float inv = 1.0f / sum;
#pragma unroll
        for (int jj = 0; jj < 4; jj++)
            s[r*128 + lane + 32*jj] = v[jj] * inv;
    }
    __syncthreads();

    // V tile (compound rows from g_cv) reuses kt
    for (int i = tid; i < 128*64; i += 256) {
        int row = i >> 6;
        if (row < cr4) {
            int kq = (i & 63) << 2;
            int gi = comp_idx[b*MCn + row];
            *(float4*)&kt[row*260 + kq] = *(const float4*)(g_cv + (size_t)gi*256 + kq);
        }
    }
    __syncthreads();

    float accO[4][8] = {};
#pragma unroll 2
    for (int c = 0; c < cr4; c += 4) {
        float pr[4][4];
#pragma unroll
        for (int i = 0; i < 4; i++) {
            float4 p = *(const float4*)&s[(4*w+i)*128 + c];
            pr[i][0]=p.x; pr[i][1]=p.y; pr[i][2]=p.z; pr[i][3]=p.w;
        }
#pragma unroll
        for (int cc = 0; cc < 4; cc++) {
            float4 v0 = *(const float4*)&kt[(c+cc)*260 + lane*4];
            float4 v1 = *(const float4*)&kt[(c+cc)*260 + 128 + lane*4];
#pragma unroll
            for (int i = 0; i < 4; i++) {
                float p = pr[i][cc];
                accO[i][0] += p*v0.x; accO[i][1] += p*v0.y;
                accO[i][2] += p*v0.z; accO[i][3] += p*v0.w;
                accO[i][4] += p*v1.x; accO[i][5] += p*v1.y;
                accO[i][6] += p*v1.z; accO[i][7] += p*v1.w;
            }
        }
    }
#pragma unroll
    for (int i = 0; i < 4; i++) {
        size_t base = (size_t)(b*MPn + r0 + 4*w + i)*256;
        *(float4*)(g_pf + base + lane*4)       = make_float4(accO[i][0],accO[i][1],accO[i][2],accO[i][3]);
        *(float4*)(g_pf + base + 128 + lane*4) = make_float4(accO[i][4],accO[i][5],accO[i][6],accO[i][7]);
    }
}

// ---------------- block reductions ----------------
__device__ __forceinline__ float blkMax(float v, float* red) {
#pragma unroll
    for (int o = 16; o; o >>= 1) v = fmaxf(v, __shfl_xor_sync(0xffffffffu, v, o));
    int w = threadIdx.x >> 5, l = threadIdx.x & 31;
    if (l == 0) red[w] = v;
    __syncthreads();
    if (threadIdx.x < 8) {
        float x = red[threadIdx.x];
#pragma unroll
        for (int o = 4; o; o >>= 1) x = fmaxf(x, __shfl_xor_sync(0x000000ffu, x, o));
        if (threadIdx.x == 0) red[0] = x;
    }
    __syncthreads();
    float r = red[0];
    __syncthreads();
    return r;
}

__device__ __forceinline__ float blkSum(float v, float* red) {
#pragma unroll
    for (int o = 16; o; o >>= 1) v += __shfl_xor_sync(0xffffffffu, v, o);
    int w = threadIdx.x >> 5, l = threadIdx.x & 31;
    if (l == 0) red[w] = v;
    __syncthreads();
    if (threadIdx.x < 8) {
        float x = red[threadIdx.x];
#pragma unroll
        for (int o = 4; o; o >>= 1) x += __shfl_xor_sync(0x000000ffu, x, o);
        if (threadIdx.x == 0) red[0] = x;
    }
    __syncthreads();
    float r = red[0];
    __syncthreads();
    return r;
}

// ---------------- finalize ----------------
__global__ void __launch_bounds__(256)
finalize_k(const int* __restrict__ comp_lens, const int* __restrict__ prot_lens,
           float* __restrict__ out)
{
    __shared__ float wc[128];
    __shared__ float wp[256];
    __shared__ float red[32];
    const int b = blockIdx.x, t = threadIdx.x;
    const int clen = comp_lens[b], plen = prot_lens[b];

    float x = -1e30f;
    if (t < 128 && t < clen) x = g_impc[b*MCn + t];
    float mx = blkMax(x, red);
    float e = (t < 128) ? __expf(x - mx) : 0.f;
    float sm = blkSum(e, red);
    if (t < 128) wc[t] = e / sm;

    float x2 = (t < plen) ? g_impp[b*MPn + t] : -1e30f;
    float mx2 = blkMax(x2, red);
    float e2 = __expf(x2 - mx2);
    float sm2 = blkSum(e2, red);
    wp[t] = e2 / sm2;
    __syncthreads();

    float h = 0.f;
    for (int n = 0; n < clen; n++)
        h += wc[n] * g_gc[(b*MCn + n)*256 + t];
    float dd = 0.f;
    for (int m = 0; m < plen; m++)
        dd += wp[m] * g_gp[(b*MPn + m)*256 + t];
    float logit = blkSum(h * dd, red);
    if (t == 0) out[b] = 1.0f / (1.0f + __expf(-logit));
}

// ---------------- host launch ----------------
extern "C" void kernel_launch(void* const* d_in, const int* in_sizes, int n_in,
                              void* d_out, int out_size)
{
    const float* comp_emb = (const float*)d_in[0];
    const float* prot_emb = (const float*)d_in[1];
    const float* Wq_c = (const float*)d_in[2];  const float* bq_c = (const float*)d_in[3];
    const float* Wk_c = (const float*)d_in[4];  const float* bk_c = (const float*)d_in[5];
    const float* Wv_c = (const float*)d_in[6];  const float* bv_c = (const float*)d_in[7];
    const float* Wq_p = (const float*)d_in[8];  const float* bq_p = (const float*)d_in[9];
    const float* Wk_p = (const float*)d_in[10]; const float* bk_p = (const float*)d_in[11];
    const float* Wv_p = (const float*)d_in[12]; const float* bv_p = (const float*)d_in[13];
    const float* Wg_c = (const float*)d_in[14]; const float* bg_c = (const float*)d_in[15];
    const float* Wg_p = (const float*)d_in[16]; const float* bg_p = (const float*)d_in[17];
    const int* comp_idx  = (const int*)d_in[18];
    const int* prot_idx  = (const int*)d_in[19];
    const int* comp_lens = (const int*)d_in[20];
    const int* prot_lens = (const int*)d_in[21];
    float* out = (float*)d_out;

    const int NC = in_sizes[0] / 256;
    const int NP = in_sizes[1] / 256;

    float *p_cq, *p_ck, *p_cv, *p_pq, *p_pk, *p_pv, *p_cf, *p_pf, *p_gc, *p_gp;
    cudaGetSymbolAddress((void**)&p_cq, g_cq);
    cudaGetSymbolAddress((void**)&p_ck, g_ck);
    cudaGetSymbolAddress((void**)&p_cv, g_cv);
    cudaGetSymbolAddress((void**)&p_pq, g_pq);
    cudaGetSymbolAddress((void**)&p_pk, g_pk);
    cudaGetSymbolAddress((void**)&p_pv, g_pv);
    cudaGetSymbolAddress((void**)&p_cf, g_cf);
    cudaGetSymbolAddress((void**)&p_pf, g_pf);
    cudaGetSymbolAddress((void**)&p_gc, g_gc);
    cudaGetSymbolAddress((void**)&p_gp, g_gp);

    const int SMEM_CP = (32*260 + 32*256 + 128*260) * 4;   // 199168
    const int SMEM_PC = (32*260 + 32*128 + 128*260) * 4;   // 182784
    cudaFuncSetAttribute(att_cp, cudaFuncAttributeMaxDynamicSharedMemorySize, SMEM_CP);
    cudaFuncSetAttribute(att_pc, cudaFuncAttributeMaxDynamicSharedMemorySize, SMEM_PC);

    init_impp_k<<<64, 1024>>>();

    gemm3<<<dim3(4, (NC + 127) / 128, 3), 256>>>(comp_emb,
        Wq_c, bq_c, p_cq,  Wk_c, bk_c, p_ck,  Wv_c, bv_c, p_cv, NC);
    gemm3<<<dim3(4, (NP + 127) / 128, 3), 256>>>(prot_emb,
        Wq_p, bq_p, p_pq,  Wk_p, bk_p, p_pk,  Wv_p, bv_p, p_pv, NP);

    att_cp<<<dim3(4, BATCH), 256, SMEM_CP>>>(comp_idx, prot_idx, comp_lens, prot_lens);
    att_pc<<<dim3(8, BATCH), 256, SMEM_PC>>>(comp_idx, prot_idx, comp_lens, prot_lens);

    gemmg<MCn><<<dim3(4, (BATCH*MCn)/128), 256>>>(p_cf, Wg_c, bg_c, p_gc, comp_lens);
    gemmg<MPn><<<dim3(4, (BATCH*MPn)/128), 256>>>(p_pf, Wg_p, bg_p, p_gp, prot_lens);

    finalize_k<<<BATCH, 256>>>(comp_lens, prot_lens, out);
}

// round 12
// speedup vs baseline: 1.5505x; 1.0132x over previous
#include <cuda_runtime.h>

#define DIM   256
#define BATCH 256
#define MCn   128
#define MPn   256
#define NMAX  20000

// ---------------- static device scratch ----------------
__device__ float g_cq[NMAX*DIM];
__device__ float g_ck[NMAX*DIM];
__device__ float g_cv[NMAX*DIM];
__device__ float g_pq[NMAX*DIM];
__device__ float g_pk[NMAX*DIM];
__device__ float g_pv[NMAX*DIM];
__device__ float g_cf[BATCH*MCn*DIM];   // comp_fused (pre-gate)
__device__ float g_pf[BATCH*MPn*DIM];   // prot_fused (pre-gate)
__device__ float g_gc[BATCH*MCn*DIM];   // gated comp_fused
__device__ float g_gp[BATCH*MPn*DIM];   // gated prot_fused
__device__ float g_impc[BATCH*MCn];
__device__ float g_impp[BATCH*MPn];

__global__ void init_impp_k() {
    int i = blockIdx.x * blockDim.x + threadIdx.x;
    if (i < BATCH*MPn) g_impp[i] = 0.0f;
}

// ---------------- projection GEMM: 3 outputs per launch ----------------
// Tile 128(M) x 64(N), 256 threads, 8x4 micro, double-buffered k-chunks of 16.
__global__ void __launch_bounds__(256, 3)
gemm3(const float* __restrict__ X,
      const float* __restrict__ W0, const float* __restrict__ bz0, float* __restrict__ O0,
      const float* __restrict__ W1, const float* __restrict__ bz1, float* __restrict__ O1,
      const float* __restrict__ W2, const float* __restrict__ bz2, float* __restrict__ O2,
      int M)
{
    __shared__ float sX[2][16][132];
    __shared__ float sW[2][16][68];
    const float* W; const float* bias; float* Out;
    if (blockIdx.z == 0)      { W = W0; bias = bz0; Out = O0; }
    else if (blockIdx.z == 1) { W = W1; bias = bz1; Out = O1; }
    else                      { W = W2; bias = bz2; Out = O2; }
    const int tid = threadIdx.x;
    const int bm = blockIdx.y * 128;
    const int bn = blockIdx.x * 64;
    const int ty = tid >> 4, tx = tid & 15;
    const int xr = tid >> 1, xk = (tid & 1) * 8;
    const int wr = tid & 63, wk = (tid >> 6) * 4;
    const float* xp = X + (size_t)(bm + xr) * 256 + xk;
    const float* wp = W + (size_t)(bn + wr) * 256 + wk;
    const bool xv = (bm + xr) < M;

    float4 rx0 = xv ? *(const float4*)xp       : make_float4(0.f,0.f,0.f,0.f);
    float4 rx1 = xv ? *(const float4*)(xp + 4) : make_float4(0.f,0.f,0.f,0.f);
    float4 rw0 = *(const float4*)wp;
    sX[0][xk+0][xr]=rx0.x; sX[0][xk+1][xr]=rx0.y; sX[0][xk+2][xr]=rx0.z; sX[0][xk+3][xr]=rx0.w;
    sX[0][xk+4][xr]=rx1.x; sX[0][xk+5][xr]=rx1.y; sX[0][xk+6][xr]=rx1.z; sX[0][xk+7][xr]=rx1.w;
    sW[0][wk+0][wr]=rw0.x; sW[0][wk+1][wr]=rw0.y; sW[0][wk+2][wr]=rw0.z; sW[0][wk+3][wr]=rw0.w;
    __syncthreads();

    float acc[8][4] = {};
#pragma unroll 1
    for (int s = 0; s < 16; s++) {
        const int cur = s & 1;
        if (s < 15) {
            const float* xq = xp + (s+1)*16;
            rx0 = xv ? *(const float4*)xq       : make_float4(0.f,0.f,0.f,0.f);
            rx1 = xv ? *(const float4*)(xq + 4) : make_float4(0.f,0.f,0.f,0.f);
            rw0 = *(const float4*)(wp + (s+1)*16);
        }
#pragma unroll
        for (int k = 0; k < 16; k++) {
            float4 a0 = *(const float4*)&sX[cur][k][ty*8];
            float4 a1 = *(const float4*)&sX[cur][k][ty*8+4];
            float4 bq = *(const float4*)&sW[cur][k][tx*4];
            float av[8] = {a0.x,a0.y,a0.z,a0.w,a1.x,a1.y,a1.z,a1.w};
            float bv[4] = {bq.x,bq.y,bq.z,bq.w};
#pragma unroll
            for (int i = 0; i < 8; i++)
#pragma unroll
                for (int j = 0; j < 4; j++) acc[i][j] += av[i]*bv[j];
        }
        if (s < 15) {
            const int nxt = cur ^ 1;
            sX[nxt][xk+0][xr]=rx0.x; sX[nxt][xk+1][xr]=rx0.y; sX[nxt][xk+2][xr]=rx0.z; sX[nxt][xk+3][xr]=rx0.w;
            sX[nxt][xk+4][xr]=rx1.x; sX[nxt][xk+5][xr]=rx1.y; sX[nxt][xk+6][xr]=rx1.z; sX[nxt][xk+7][xr]=rx1.w;
            sW[nxt][wk+0][wr]=rw0.x; sW[nxt][wk+1][wr]=rw0.y; sW[nxt][wk+2][wr]=rw0.z; sW[nxt][wk+3][wr]=rw0.w;
            __syncthreads();
        }
    }
    float4 bb = *(const float4*)(bias + bn + tx*4);
    float bvv[4] = {bb.x, bb.y, bb.z, bb.w};
#pragma unroll
    for (int i = 0; i < 8; i++) {
        int r = bm + ty*8 + i;
        if (r < M)
            *(float4*)(Out + (size_t)r*256 + bn + tx*4) =
                make_float4(acc[i][0]+bvv[0], acc[i][1]+bvv[1],
                            acc[i][2]+bvv[2], acc[i][3]+bvv[3]);
    }
}

// ---------------- gated GEMM: Out = X * sigmoid(X@W^T + b), length-skipped ----------------
template<int SEQ>
__global__ void __launch_bounds__(256, 3)
gemmg(const float* __restrict__ X, const float* __restrict__ W,
      const float* __restrict__ bias, float* __restrict__ Out,
      const int* __restrict__ lens)
{
    __shared__ float sX[2][16][132];
    __shared__ float sW[2][16][68];
    const int tid = threadIdx.x;
    const int bm = blockIdx.y * 128;
    const int bn = blockIdx.x * 64;
    const int b = bm / SEQ;
    const int lenloc = lens[b] - (bm - b*SEQ);
    if (lenloc <= 0) return;
    const bool wvalid = ((tid >> 5) * 16) < lenloc;   // warp rows 16w..16w+15
    const int ty = tid >> 4, tx = tid & 15;
    const int xr = tid >> 1, xk = (tid & 1) * 8;
    const int wr = tid & 63, wk = (tid >> 6) * 4;
    const float* xp = X + (size_t)(bm + xr) * 256 + xk;
    const float* wp = W + (size_t)(bn + wr) * 256 + wk;

    float4 rx0 = *(const float4*)xp;
    float4 rx1 = *(const float4*)(xp + 4);
    float4 rw0 = *(const float4*)wp;
    sX[0][xk+0][xr]=rx0.x; sX[0][xk+1][xr]=rx0.y; sX[0][xk+2][xr]=rx0.z; sX[0][xk+3][xr]=rx0.w;
    sX[0][xk+4][xr]=rx1.x; sX[0][xk+5][xr]=rx1.y; sX[0][xk+6][xr]=rx1.z; sX[0][xk+7][xr]=rx1.w;
    sW[0][wk+0][wr]=rw0.x; sW[0][wk+1][wr]=rw0.y; sW[0][wk+2][wr]=rw0.z; sW[0][wk+3][wr]=rw0.w;
    __syncthreads();

    float acc[8][4] = {};
#pragma unroll 1
    for (int s = 0; s < 16; s++) {
        const int cur = s & 1;
        if (s < 15) {
            const float* xq = xp + (s+1)*16;
            rx0 = *(const float4*)xq;
            rx1 = *(const float4*)(xq + 4);
            rw0 = *(const float4*)(wp + (s+1)*16);
        }
        if (wvalid) {
#pragma unroll
            for (int k = 0; k < 16; k++) {
                float4 a0 = *(const float4*)&sX[cur][k][ty*8];
                float4 a1 = *(const float4*)&sX[cur][k][ty*8+4];
                float4 bq = *(const float4*)&sW[cur][k][tx*4];
                float av[8] = {a0.x,a0.y,a0.z,a0.w,a1.x,a1.y,a1.z,a1.w};
                float bv[4] = {bq.x,bq.y,bq.z,bq.w};
#pragma unroll
                for (int i = 0; i < 8; i++)
#pragma unroll
                    for (int j = 0; j < 4; j++) acc[i][j] += av[i]*bv[j];
            }
        }
        if (s < 15) {
            const int nxt = cur ^ 1;
            sX[nxt][xk+0][xr]=rx0.x; sX[nxt][xk+1][xr]=rx0.y; sX[nxt][xk+2][xr]=rx0.z; sX[nxt][xk+3][xr]=rx0.w;
            sX[nxt][xk+4][xr]=rx1.x; sX[nxt][xk+5][xr]=rx1.y; sX[nxt][xk+6][xr]=rx1.z; sX[nxt][xk+7][xr]=rx1.w;
            sW[nxt][wk+0][wr]=rw0.x; sW[nxt][wk+1][wr]=rw0.y; sW[nxt][wk+2][wr]=rw0.z; sW[nxt][wk+3][wr]=rw0.w;
            __syncthreads();
        }
    }
    if (!wvalid) return;
    float4 bb = *(const float4*)(bias + bn + tx*4);
    float bvv[4] = {bb.x, bb.y, bb.z, bb.w};
#pragma unroll
    for (int i = 0; i < 8; i++) {
        int r = bm + ty*8 + i;
        float4 xr4 = *(const float4*)(X + (size_t)r*256 + bn + tx*4);
        float xa[4] = {xr4.x, xr4.y, xr4.z, xr4.w};
        float o[4];
#pragma unroll
        for (int j = 0; j < 4; j++) {
            float logit = acc[i][j] + bvv[j];
            o[j] = xa[j] * (1.0f / (1.0f + __expf(-logit)));
        }
        *(float4*)(Out + (size_t)r*256 + bn + tx*4) = make_float4(o[0],o[1],o[2],o[3]);
    }
}

// ---------------- compound->protein attention (512 threads, 16 warps) ----------------
// smem: q[32][260], s[32][256], kt[128][260]; warp w owns rows 2w, 2w+1
__global__ void __launch_bounds__(512)
att_cp(const int* __restrict__ comp_idx, const int* __restrict__ prot_idx,
       const int* __restrict__ comp_lens, const int* __restrict__ prot_lens)
{
    extern __shared__ float smem[];
    float* q  = smem;                   // 32*260
    float* s  = smem + 32*260;          // 32*256
    float* kt = smem + 32*260 + 32*256; // 128*260
    const int b = blockIdx.y;
    const int r0 = blockIdx.x * 32;
    const int tid = threadIdx.x, lane = tid & 31, w = tid >> 5;
    const int clen = comp_lens[b], plen = prot_lens[b];
    if (r0 >= clen) return;

    // gather q rows (scaled by 1/16)
    for (int i = tid; i < 32*64; i += 512) {
        int row = i >> 6, kq = (i & 63) << 2;
        int gi = comp_idx[b*MCn + r0 + row];
        float4 v = *(const float4*)(g_cq + (size_t)gi*256 + kq);
        v.x *= 0.0625f; v.y *= 0.0625f; v.z *= 0.0625f; v.w *= 0.0625f;
        *(float4*)&q[row*260 + kq] = v;
    }
    __syncthreads();

    // scores in 128-col chunks
    for (int m0 = 0; m0 < plen; m0 += 128) {
        int mrows = plen - m0; if (mrows > 128) mrows = 128;
        int mr4 = (mrows + 3) & ~3;
        for (int i = tid; i < 128*64; i += 512) {
            int row = i >> 6;
            if (row < mr4) {
                int kq = (i & 63) << 2;
                int gi = prot_idx[b*MPn + m0 + row];
                *(float4*)&kt[row*260 + kq] = *(const float4*)(g_pk + (size_t)gi*256 + kq);
            }
        }
        __syncthreads();
        float acc[2][4] = {};
#pragma unroll 2
        for (int k = 0; k < 256; k += 4) {
            float4 qv[2];
#pragma unroll
            for (int i = 0; i < 2; i++) qv[i] = *(const float4*)&q[(2*w+i)*260 + k];
#pragma unroll
            for (int j = 0; j < 4; j++) {
                if (32*j < mrows) {
                    float4 kv = *(const float4*)&kt[(lane + 32*j)*260 + k];
#pragma unroll
                    for (int i = 0; i < 2; i++)
                        acc[i][j] += qv[i].x*kv.x + qv[i].y*kv.y + qv[i].z*kv.z + qv[i].w*kv.w;
                }
            }
        }
#pragma unroll
        for (int i = 0; i < 2; i++)
#pragma unroll
            for (int j = 0; j < 4; j++)
                s[(2*w+i)*256 + m0 + lane + 32*j] = acc[i][j];
        __syncthreads();
    }

    // masked softmax per row + imp_c (warp w owns rows 2w, 2w+1)
#pragma unroll
    for (int i = 0; i < 2; i++) {
        int r = 2*w + i;
        bool rvalid = (r0 + r) < clen;
        float v[8];
        float mx = -3.4e38f;
#pragma unroll
        for (int jj = 0; jj < 8; jj++) {
            int m = lane + 32*jj;
            float sc = s[r*256 + m];
            if (!rvalid || m >= plen) sc = -1e9f;
            v[jj] = sc; mx = fmaxf(mx, sc);
        }
#pragma unroll
        for (int o = 16; o; o >>= 1) mx = fmaxf(mx, __shfl_xor_sync(0xffffffffu, mx, o));
        float sum = 0.f;
#pragma unroll
        for (int jj = 0; jj < 8; jj++) { v[jj] = __expf(v[jj] - mx); sum += v[jj]; }
#pragma unroll
        for (int o = 16; o; o >>= 1) sum += __shfl_xor_sync(0xffffffffu, sum, o);
        float inv = 1.0f / sum;
        float pmax = 0.f;
#pragma unroll
        for (int jj = 0; jj < 8; jj++) {
            float p = v[jj] * inv;
            s[r*256 + lane + 32*jj] = p;
            pmax = fmaxf(pmax, p);
        }
#pragma unroll
        for (int o = 16; o; o >>= 1) pmax = fmaxf(pmax, __shfl_xor_sync(0xffffffffu, pmax, o));
        if (lane == 0) g_impc[b*MCn + r0 + r] = pmax;
    }
    __syncthreads();

    // imp_p column max over valid rows (columns 0..255 handled by tid<256)
    if (tid < 256) {
        int nval = clen - r0; if (nval > 32) nval = 32;
        float vmax = 0.f;
        for (int r = 0; r < nval; r++) vmax = fmaxf(vmax, s[r*256 + tid]);
        atomicMax((int*)&g_impp[b*MPn + tid], __float_as_int(vmax));
    }

    // PV in 128-col chunks; warp w computes rows 2w,2w+1; lane owns d=lane*4..+3, 128+lane*4..+3
    float accO[2][8] = {};
    for (int c0 = 0; c0 < plen; c0 += 128) {
        int crows = plen - c0; if (crows > 128) crows = 128;
        int cr4 = (crows + 3) & ~3;
        __syncthreads();
        for (int i = tid; i < 128*64; i += 512) {
            int row = i >> 6;
            if (row < cr4) {
                int kq = (i & 63) << 2;
                int gi = prot_idx[b*MPn + c0 + row];
                *(float4*)&kt[row*260 + kq] = *(const float4*)(g_pv + (size_t)gi*256 + kq);
            }
        }
        __syncthreads();
#pragma unroll 2
        for (int c = 0; c < cr4; c += 4) {
            float pr[2][4];
#pragma unroll
            for (int i = 0; i < 2; i++) {
                float4 p = *(const float4*)&s[(2*w+i)*256 + c0 + c];
                pr[i][0]=p.x; pr[i][1]=p.y; pr[i][2]=p.z; pr[i][3]=p.w;
            }
#pragma unroll
            for (int cc = 0; cc < 4; cc++) {
                float4 v0 = *(const float4*)&kt[(c+cc)*260 + lane*4];
                float4 v1 = *(const float4*)&kt[(c+cc)*260 + 128 + lane*4];
#pragma unroll
                for (int i = 0; i < 2; i++) {
                    float p = pr[i][cc];
                    accO[i][0] += p*v0.x; accO[i][1] += p*v0.y;
                    accO[i][2] += p*v0.z; accO[i][3] += p*v0.w;
                    accO[i][4] += p*v1.x; accO[i][5] += p*v1.y;
                    accO[i][6] += p*v1.z; accO[i][7] += p*v1.w;
                }
            }
        }
    }
#pragma unroll
    for (int i = 0; i < 2; i++) {
        size_t base = (size_t)(b*MCn + r0 + 2*w + i)*256;
        *(float4*)(g_cf + base + lane*4)       = make_float4(accO[i][0],accO[i][1],accO[i][2],accO[i][3]);
        *(float4*)(g_cf + base + 128 + lane*4) = make_float4(accO[i][4],accO[i][5],accO[i][6],accO[i][7]);
    }
}

// ---------------- protein->compound attention (512 threads, 16 warps) ----------------
// smem: q[32][260], s[32][128], kt[128][260]; warp w owns rows 2w, 2w+1
__global__ void __launch_bounds__(512)
att_pc(const int* __restrict__ comp_idx, const int* __restrict__ prot_idx,
       const int* __restrict__ comp_lens, const int* __restrict__ prot_lens)
{
    extern __shared__ float smem[];
    float* q  = smem;                   // 32*260
    float* s  = smem + 32*260;          // 32*128
    float* kt = smem + 32*260 + 32*128; // 128*260
    const int b = blockIdx.y;
    const int r0 = blockIdx.x * 32;
    const int tid = threadIdx.x, lane = tid & 31, w = tid >> 5;
    const int clen = comp_lens[b], plen = prot_lens[b];
    if (r0 >= plen) return;
    const int cr4 = (clen + 3) & ~3;

    for (int i = tid; i < 32*64; i += 512) {
        int row = i >> 6, kq = (i & 63) << 2;
        int gi = prot_idx[b*MPn + r0 + row];
        float4 v = *(const float4*)(g_pq + (size_t)gi*256 + kq);
        v.x *= 0.0625f; v.y *= 0.0625f; v.z *= 0.0625f; v.w *= 0.0625f;
        *(float4*)&q[row*260 + kq] = v;
    }
    // K tile (compound rows)
    for (int i = tid; i < 128*64; i += 512) {
        int row = i >> 6;
        if (row < cr4) {
            int kq = (i & 63) << 2;
            int gi = comp_idx[b*MCn + row];
            *(float4*)&kt[row*260 + kq] = *(const float4*)(g_ck + (size_t)gi*256 + kq);
        }
    }
    __syncthreads();

    {
        float acc[2][4] = {};
#pragma unroll 2
        for (int k = 0; k < 256; k += 4) {
            float4 qv[2];
#pragma unroll
            for (int i = 0; i < 2; i++) qv[i] = *(const float4*)&q[(2*w+i)*260 + k];
#pragma unroll
            for (int j = 0; j < 4; j++) {
                if (32*j < clen) {
                    float4 kv = *(const float4*)&kt[(lane + 32*j)*260 + k];
#pragma unroll
                    for (int i = 0; i < 2; i++)
                        acc[i][j] += qv[i].x*kv.x + qv[i].y*kv.y + qv[i].z*kv.z + qv[i].w*kv.w;
                }
            }
        }
#pragma unroll
        for (int i = 0; i < 2; i++)
#pragma unroll
            for (int j = 0; j < 4; j++)
                s[(2*w+i)*128 + lane + 32*j] = acc[i][j];
    }

    // masked softmax over 128 compound cols (warp-private rows)
#pragma unroll
    for (int i = 0; i < 2; i++) {
        int r = 2*w + i;
        bool rvalid = (r0 + r) < plen;
        float v[4];
        float mx = -3.4e38f;
#pragma unroll
        for (int jj = 0; jj < 4; jj++) {
            int n = lane + 32*jj;
            float sc = s[r*128 + n];
            if (!rvalid || n >= clen) sc = -1e9f;
            v[jj] = sc; mx = fmaxf(mx, sc);
        }
#pragma unroll
        for (int o = 16; o; o >>= 1) mx = fmaxf(mx, __shfl_xor_sync(0xffffffffu, mx, o));
        float sum = 0.f;
#pragma unroll
        for (int jj = 0; jj < 4; jj++) { v[jj] = __expf(v[jj] - mx); sum += v[jj]; }
#pragma unroll
        for (int o = 16; o; o >>= 1) sum += __shfl_xor_sync(0xffffffffu, sum, o);
        float inv = 1.0f / sum;
#pragma unroll
        for (int jj = 0; jj < 4; jj++)
            s[r*128 + lane + 32*jj] = v[jj] * inv;
    }
    __syncthreads();

    // V tile (compound rows from g_cv) reuses kt
    for (int i = tid; i < 128*64; i += 512) {
        int row = i >> 6;
        if (row < cr4) {
            int kq = (i & 63) << 2;
            int gi = comp_idx[b*MCn + row];
            *(float4*)&kt[row*260 + kq] = *(const float4*)(g_cv + (size_t)gi*256 + kq);
        }
    }
    __syncthreads();

    float accO[2][8] = {};
#pragma unroll 2
    for (int c = 0; c < cr4; c += 4) {
        float pr[2][4];
#pragma unroll
        for (int i = 0; i < 2; i++) {
            float4 p = *(const float4*)&s[(2*w+i)*128 + c];
            pr[i][0]=p.x; pr[i][1]=p.y; pr[i][2]=p.z; pr[i][3]=p.w;
        }
#pragma unroll
        for (int cc = 0; cc < 4; cc++) {
            float4 v0 = *(const float4*)&kt[(c+cc)*260 + lane*4];
            float4 v1 = *(const float4*)&kt[(c+cc)*260 + 128 + lane*4];
#pragma unroll
            for (int i = 0; i < 2; i++) {
                float p = pr[i][cc];
                accO[i][0] += p*v0.x; accO[i][1] += p*v0.y;
                accO[i][2] += p*v0.z; accO[i][3] += p*v0.w;
                accO[i][4] += p*v1.x; accO[i][5] += p*v1.y;
                accO[i][6] += p*v1.z; accO[i][7] += p*v1.w;
            }
        }
    }
#pragma unroll
    for (int i = 0; i < 2; i++) {
        size_t base = (size_t)(b*MPn + r0 + 2*w + i)*256;
        *(float4*)(g_pf + base + lane*4)       = make_float4(accO[i][0],accO[i][1],accO[i][2],accO[i][3]);
        *(float4*)(g_pf + base + 128 + lane*4) = make_float4(accO[i][4],accO[i][5],accO[i][6],accO[i][7]);
    }
}

// ---------------- block reductions ----------------
__device__ __forceinline__ float blkMax(float v, float* red) {
#pragma unroll
    for (int o = 16; o; o >>= 1) v = fmaxf(v, __shfl_xor_sync(0xffffffffu, v, o));
    int w = threadIdx.x >> 5, l = threadIdx.x & 31;
    if (l == 0) red[w] = v;
    __syncthreads();
    if (threadIdx.x < 8) {
        float x = red[threadIdx.x];
#pragma unroll
        for (int o = 4; o; o >>= 1) x = fmaxf(x, __shfl_xor_sync(0x000000ffu, x, o));
        if (threadIdx.x == 0) red[0] = x;
    }
    __syncthreads();
    float r = red[0];
    __syncthreads();
    return r;
}

__device__ __forceinline__ float blkSum(float v, float* red) {
#pragma unroll
    for (int o = 16; o; o >>= 1) v += __shfl_xor_sync(0xffffffffu, v, o);
    int w = threadIdx.x >> 5, l = threadIdx.x & 31;
    if (l == 0) red[w] = v;
    __syncthreads();
    if (threadIdx.x < 8) {
        float x = red[threadIdx.x];
#pragma unroll
        for (int o = 4; o; o >>= 1) x += __shfl_xor_sync(0x000000ffu, x, o);
        if (threadIdx.x == 0) red[0] = x;
    }
    __syncthreads();
    float r = red[0];
    __syncthreads();
    return r;
}

// ---------------- finalize ----------------
__global__ void __launch_bounds__(256)
finalize_k(const int* __restrict__ comp_lens, const int* __restrict__ prot_lens,
           float* __restrict__ out)
{
    __shared__ float wc[128];
    __shared__ float wp[256];
    __shared__ float red[32];
    const int b = blockIdx.x, t = threadIdx.x;
    const int clen = comp_lens[b], plen = prot_lens[b];

    float x = -1e30f;
    if (t < 128 && t < clen) x = g_impc[b*MCn + t];
    float mx = blkMax(x, red);
    float e = (t < 128) ? __expf(x - mx) : 0.f;
    float sm = blkSum(e, red);
    if (t < 128) wc[t] = e / sm;

    float x2 = (t < plen) ? g_impp[b*MPn + t] : -1e30f;
    float mx2 = blkMax(x2, red);
    float e2 = __expf(x2 - mx2);
    float sm2 = blkSum(e2, red);
    wp[t] = e2 / sm2;
    __syncthreads();

    float h = 0.f;
    for (int n = 0; n < clen; n++)
        h += wc[n] * g_gc[(b*MCn + n)*256 + t];
    float dd = 0.f;
    for (int m = 0; m < plen; m++)
        dd += wp[m] * g_gp[(b*MPn + m)*256 + t];
    float logit = blkSum(h * dd, red);
    if (t == 0) out[b] = 1.0f / (1.0f + __expf(-logit));
}

// ---------------- host launch ----------------
extern "C" void kernel_launch(void* const* d_in, const int* in_sizes, int n_in,
                              void* d_out, int out_size)
{
    const float* comp_emb = (const float*)d_in[0];
    const float* prot_emb = (const float*)d_in[1];
    const float* Wq_c = (const float*)d_in[2];  const float* bq_c = (const float*)d_in[3];
    const float* Wk_c = (const float*)d_in[4];  const float* bk_c = (const float*)d_in[5];
    const float* Wv_c = (const float*)d_in[6];  const float* bv_c = (const float*)d_in[7];
    const float* Wq_p = (const float*)d_in[8];  const float* bq_p = (const float*)d_in[9];
    const float* Wk_p = (const float*)d_in[10]; const float* bk_p = (const float*)d_in[11];
    const float* Wv_p = (const float*)d_in[12]; const float* bv_p = (const float*)d_in[13];
    const float* Wg_c = (const float*)d_in[14]; const float* bg_c = (const float*)d_in[15];
    const float* Wg_p = (const float*)d_in[16]; const float* bg_p = (const float*)d_in[17];
    const int* comp_idx  = (const int*)d_in[18];
    const int* prot_idx  = (const int*)d_in[19];
    const int* comp_lens = (const int*)d_in[20];
    const int* prot_lens = (const int*)d_in[21];
    float* out = (float*)d_out;

    const int NC = in_sizes[0] / 256;
    const int NP = in_sizes[1] / 256;

    float *p_cq, *p_ck, *p_cv, *p_pq, *p_pk, *p_pv, *p_cf, *p_pf, *p_gc, *p_gp;
    cudaGetSymbolAddress((void**)&p_cq, g_cq);
    cudaGetSymbolAddress((void**)&p_ck, g_ck);
    cudaGetSymbolAddress((void**)&p_cv, g_cv);
    cudaGetSymbolAddress((void**)&p_pq, g_pq);
    cudaGetSymbolAddress((void**)&p_pk, g_pk);
    cudaGetSymbolAddress((void**)&p_pv, g_pv);
    cudaGetSymbolAddress((void**)&p_cf, g_cf);
    cudaGetSymbolAddress((void**)&p_pf, g_pf);
    cudaGetSymbolAddress((void**)&p_gc, g_gc);
    cudaGetSymbolAddress((void**)&p_gp, g_gp);

    const int SMEM_CP = (32*260 + 32*256 + 128*260) * 4;   // 199168
    const int SMEM_PC = (32*260 + 32*128 + 128*260) * 4;   // 182784
    cudaFuncSetAttribute(att_cp, cudaFuncAttributeMaxDynamicSharedMemorySize, SMEM_CP);
    cudaFuncSetAttribute(att_pc, cudaFuncAttributeMaxDynamicSharedMemorySize, SMEM_PC);

    init_impp_k<<<64, 1024>>>();

    gemm3<<<dim3(4, (NC + 127) / 128, 3), 256>>>(comp_emb,
        Wq_c, bq_c, p_cq,  Wk_c, bk_c, p_ck,  Wv_c, bv_c, p_cv, NC);
    gemm3<<<dim3(4, (NP + 127) / 128, 3), 256>>>(prot_emb,
        Wq_p, bq_p, p_pq,  Wk_p, bk_p, p_pk,  Wv_p, bv_p, p_pv, NP);

    att_cp<<<dim3(4, BATCH), 512, SMEM_CP>>>(comp_idx, prot_idx, comp_lens, prot_lens);
    att_pc<<<dim3(8, BATCH), 512, SMEM_PC>>>(comp_idx, prot_idx, comp_lens, prot_lens);

    gemmg<MCn><<<dim3(4, (BATCH*MCn)/128), 256>>>(p_cf, Wg_c, bg_c, p_gc, comp_lens);
    gemmg<MPn><<<dim3(4, (BATCH*MPn)/128), 256>>>(p_pf, Wg_p, bg_p, p_gp, prot_lens);

    finalize_k<<<BATCH, 256>>>(comp_lens, prot_lens, out);
}